// round 11
// baseline (speedup 1.0000x reference)
#include <cuda_runtime.h>
#include <cuda_fp16.h>
#include <cstdint>
#include <stdint.h>
#include <math.h>

#define DD 128
#define NMAX 50000
#define EMAX 800000
#define SROW 136            // smem row stride in halfs (272B, 16B-multiple)

// ---------------- scratch (static device globals) ----------------
__device__ __align__(16) __half g_S[(size_t)NMAX * DD];       // rs_out-scaled gather rows
__device__ __align__(16) __half g_agg16[(size_t)NMAX * DD];   // aggregation output (fp16)
__device__ __align__(16) float  g_token[DD];
__device__ int   g_deg_out[NMAX];
__device__ int   g_deg_in[NMAX];
__device__ float g_rs_out[NMAX];
__device__ float g_rs_in[NMAX];
__device__ int   g_maskflag[NMAX];
__device__ int   g_rowptr[NMAX + 1];
__device__ int   g_fill[NMAX];
__device__ int   g_csrc[EMAX];

// ---------------- setup kernels ----------------
__global__ void k_init(const float* __restrict__ token, float* __restrict__ tok,
                       int* __restrict__ deg_out, int* __restrict__ deg_in,
                       int* __restrict__ fill, int* __restrict__ maskflag,
                       float* __restrict__ out, int n) {
    int i = blockIdx.x * blockDim.x + threadIdx.x;
    if (i < n) { deg_out[i] = 0; deg_in[i] = 0; fill[i] = 0; maskflag[i] = 0; }
    if (i < DD) tok[i] = token[i];
    if (i == 0) out[0] = 0.f;
}

__global__ void k_deg(const int* __restrict__ src, const int* __restrict__ dst,
                      int* __restrict__ dout, int* __restrict__ din, int e) {
    int i = blockIdx.x * blockDim.x + threadIdx.x;
    if (i < e) {
        atomicAdd(&dout[src[i]], 1);
        atomicAdd(&din[dst[i]], 1);
    }
}

// ---------------- k_mid: mask mark + rsqrt norms + full exclusive scan (one block) ----------
__global__ void __launch_bounds__(1024)
k_mid(const int* __restrict__ mask_nodes, int* __restrict__ maskflag, int m,
      const int* __restrict__ dout, const int* __restrict__ din,
      float* __restrict__ ro, float* __restrict__ ri,
      int* __restrict__ rowptr, int n) {
    __shared__ int warpsum[32];
    int t = threadIdx.x;
    int lane = t & 31, wid = t >> 5;

    // elementwise: rsqrt norms
    for (int i = t; i < n; i += 1024) {
        ro[i] = rsqrtf(fmaxf((float)dout[i], 1.f));
        ri[i] = rsqrtf(fmaxf((float)din[i], 1.f));
    }
    // mask marking
    for (int i = t; i < m; i += 1024) maskflag[mask_nodes[i]] = 1;

    // exclusive scan of din -> rowptr, sequential 1024-tiles with running carry
    int carry = 0;
    int tiles = (n + 1023) / 1024;
    for (int tb = 0; tb < tiles; tb++) {
        int gi = tb * 1024 + t;
        int v = (gi < n) ? din[gi] : 0;
        int inc = v;
        #pragma unroll
        for (int o = 1; o < 32; o <<= 1) {
            int u = __shfl_up_sync(0xffffffffu, inc, o);
            if (lane >= o) inc += u;
        }
        if (lane == 31) warpsum[wid] = inc;
        __syncthreads();
        if (wid == 0) {
            int w = warpsum[lane];
            #pragma unroll
            for (int o = 1; o < 32; o <<= 1) {
                int u = __shfl_up_sync(0xffffffffu, w, o);
                if (lane >= o) w += u;
            }
            warpsum[lane] = w;
        }
        __syncthreads();
        int woff = (wid > 0) ? warpsum[wid - 1] : 0;
        if (gi < n) rowptr[gi] = carry + woff + inc - v;
        int total = warpsum[31];
        __syncthreads();        // protect warpsum before next tile overwrites
        carry += total;
    }
    if (t == 0) rowptr[n] = carry;
}

__global__ void k_fill(const int* __restrict__ src, const int* __restrict__ dst,
                       const int* __restrict__ rowptr, int* __restrict__ fill,
                       int* __restrict__ csrc, int e) {
    int i = blockIdx.x * blockDim.x + threadIdx.x;
    if (i < e) {
        int d = dst[i];
        int p = rowptr[d] + atomicAdd(&fill[d], 1);
        csrc[p] = src[i];
    }
}

// ---------------- prep: S[v] = (mask? token : x[v]) * rs_out[v] fp16 ----------------
__global__ void __launch_bounds__(256)
k_prep1(const float* __restrict__ x, const float* __restrict__ token,
        const int* __restrict__ maskflag, const float* __restrict__ rs_out,
        __half* __restrict__ S, int n) {
    int w = (blockIdx.x * blockDim.x + threadIdx.x) >> 5;
    int lane = threadIdx.x & 31;
    if (w >= n) return;
    float r = rs_out[w];
    const float* srcp = maskflag[w] ? (token + lane * 4) : (x + (size_t)w * DD + lane * 4);
    __half2 p0 = __floats2half2_rn(srcp[0] * r, srcp[1] * r);
    __half2 p1 = __floats2half2_rn(srcp[2] * r, srcp[3] * r);
    uint2 u;
    *(__half2*)&u.x = p0;
    *(__half2*)&u.y = p1;
    ((uint2*)S)[(size_t)w * 32 + lane] = u;
}

// ---------------- CSR aggregation (full) ----------------
__global__ void __launch_bounds__(256)
k_agg(const __half* __restrict__ S,
      const int* __restrict__ rowptr, const int* __restrict__ csrc,
      __half* __restrict__ agg, int n) {
    int w = (blockIdx.x * blockDim.x + threadIdx.x) >> 5;
    int lane = threadIdx.x & 31;
    if (w >= n) return;
    int beg = rowptr[w];
    int end = rowptr[w + 1];
    float4 acc = make_float4(0.f, 0.f, 0.f, 0.f);
    for (int e = beg; e < end; e++) {
        int s = csrc[e];
        uint2 u = ((const uint2*)S)[(size_t)s * 32 + lane];
        float2 f0 = __half22float2(*(__half2*)&u.x);
        float2 f1 = __half22float2(*(__half2*)&u.y);
        acc.x += f0.x; acc.y += f0.y; acc.z += f1.x; acc.w += f1.y;
    }
    uint2 o;
    *(__half2*)&o.x = __floats2half2_rn(acc.x, acc.y);
    *(__half2*)&o.y = __floats2half2_rn(acc.z, acc.w);
    ((uint2*)agg)[(size_t)w * 32 + lane] = o;
}

// ---------------- decoder aggregation (compacted over mask_nodes) ----------------
// warp j < m: gather in-edges of node mask_nodes[j], skipping masked src (zero rows),
// write to agg[j] (compacted).
__global__ void __launch_bounds__(256)
k_agg_dec(const __half* __restrict__ S,
          const int* __restrict__ rowptr, const int* __restrict__ csrc,
          const int* __restrict__ maskflag, const int* __restrict__ mask_nodes,
          __half* __restrict__ agg, int m) {
    int j = (blockIdx.x * blockDim.x + threadIdx.x) >> 5;
    int lane = threadIdx.x & 31;
    if (j >= m) return;
    int node = mask_nodes[j];
    int beg = rowptr[node];
    int end = rowptr[node + 1];
    float4 acc = make_float4(0.f, 0.f, 0.f, 0.f);
    for (int e = beg; e < end; e++) {
        int s = csrc[e];
        if (maskflag[s]) continue;        // re-masked row is zero
        uint2 u = ((const uint2*)S)[(size_t)s * 32 + lane];
        float2 f0 = __half22float2(*(__half2*)&u.x);
        float2 f1 = __half22float2(*(__half2*)&u.y);
        acc.x += f0.x; acc.y += f0.y; acc.z += f1.x; acc.w += f1.y;
    }
    uint2 o;
    *(__half2*)&o.x = __floats2half2_rn(acc.x, acc.y);
    *(__half2*)&o.y = __floats2half2_rn(acc.z, acc.w);
    ((uint2*)agg)[(size_t)j * 32 + lane] = o;
}

// ---------------- mma helper macros ----------------
#define MMA_LOOP(cacc, aBase, sWu, bRow, bKoff)                                              \
    _Pragma("unroll")                                                                         \
    for (int kb = 0; kb < 8; kb++) {                                                          \
        uint32_t a0, a1, a2, a3;                                                              \
        asm volatile("ldmatrix.sync.aligned.m8n8.x4.shared.b16 {%0,%1,%2,%3}, [%4];"         \
                     : "=r"(a0), "=r"(a1), "=r"(a2), "=r"(a3)                                 \
                     : "r"((aBase) + kb * 32));                                               \
        _Pragma("unroll")                                                                     \
        for (int ng = 0; ng < 8; ng++) {                                                      \
            uint32_t b0, b1, b2, b3;                                                          \
            uint32_t baddr = (sWu) + (uint32_t)((ng * 16 + (bRow)) * (SROW * 2) + kb * 32 + (bKoff)); \
            asm volatile("ldmatrix.sync.aligned.m8n8.x4.shared.b16 {%0,%1,%2,%3}, [%4];"     \
                         : "=r"(b0), "=r"(b1), "=r"(b2), "=r"(b3)                             \
                         : "r"(baddr));                                                       \
            int t0 = ng * 2, t1 = ng * 2 + 1;                                                 \
            asm volatile("mma.sync.aligned.m16n8k16.row.col.f32.f16.f16.f32 "                \
                         "{%0,%1,%2,%3}, {%4,%5,%6,%7}, {%8,%9}, {%0,%1,%2,%3};"             \
                         : "+f"(cacc[t0][0]), "+f"(cacc[t0][1]), "+f"(cacc[t0][2]), "+f"(cacc[t0][3]) \
                         : "r"(a0), "r"(a1), "r"(a2), "r"(a3), "r"(b0), "r"(b1));             \
            asm volatile("mma.sync.aligned.m16n8k16.row.col.f32.f16.f16.f32 "                \
                         "{%0,%1,%2,%3}, {%4,%5,%6,%7}, {%8,%9}, {%0,%1,%2,%3};"             \
                         : "+f"(cacc[t1][0]), "+f"(cacc[t1][1]), "+f"(cacc[t1][2]), "+f"(cacc[t1][3]) \
                         : "r"(a0), "r"(a1), "r"(a2), "r"(a3), "r"(b2), "r"(b3));             \
        }                                                                                     \
    }

#define STAGE_W(Wp, sW)                                                                       \
    _Pragma("unroll")                                                                         \
    for (int it = 0; it < 32; it++) {                                                         \
        int idx = it * 256 + threadIdx.x;                                                     \
        int base2 = idx * 2;                                                                  \
        int cc = base2 >> 7, kk = base2 & 127;                                                \
        float w0 = (Wp)[base2], w1 = (Wp)[base2 + 1];                                         \
        *(__half2*)&(sW)[cc * SROW + kk] = __floats2half2_rn(w0, w1);                         \
    }

#define STAGE_A(inp, sA, nrows)                                                               \
    _Pragma("unroll")                                                                         \
    for (int it = 0; it < 8; it++) {                                                          \
        int idx = it * 256 + threadIdx.x;                                                     \
        int r = idx >> 4, c8 = idx & 15;                                                      \
        uint4 v = make_uint4(0u, 0u, 0u, 0u);                                                 \
        int gr = row0 + r;                                                                    \
        if (gr < (nrows)) v = ((const uint4*)(inp))[(size_t)gr * 16 + c8];                    \
        *(uint4*)&(sA)[r * SROW + c8 * 8] = v;                                                \
    }

// ---------------- conv1 GEMM: (acc+b)*rs_in -> LN -> PReLU -> fp16 *rs_out -> S ----------
__global__ void __launch_bounds__(256, 2)
k_gemm1(const __half* __restrict__ in, __half* __restrict__ outh,
        const float* __restrict__ W, const float* __restrict__ bias,
        const float* __restrict__ rs_in, const float* __restrict__ rs_out,
        const float* __restrict__ gamma, const float* __restrict__ beta,
        const float* __restrict__ alpha, int n) {
    extern __shared__ char smraw[];
    __half* sA = (__half*)smraw;
    __half* sW = sA + 128 * SROW;
    float* sBias  = (float*)(sW + 128 * SROW);
    float* sGamma = sBias + 128;
    float* sBeta  = sGamma + 128;

    const int tid  = threadIdx.x;
    const int row0 = blockIdx.x * 128;

    STAGE_A(in, sA, n);
    STAGE_W(W, sW);
    if (tid < 128) { sBias[tid] = bias[tid]; sGamma[tid] = gamma[tid]; sBeta[tid] = beta[tid]; }
    __syncthreads();

    const int warp = tid >> 5;
    const int lane = tid & 31;
    float c[16][4];
    #pragma unroll
    for (int i = 0; i < 16; i++) { c[i][0]=0.f; c[i][1]=0.f; c[i][2]=0.f; c[i][3]=0.f; }

    uint32_t sAu = (uint32_t)__cvta_generic_to_shared(sA);
    uint32_t sWu = (uint32_t)__cvta_generic_to_shared(sW);
    uint32_t aBase = sAu + (uint32_t)((warp * 16 + (lane & 15)) * (SROW * 2) + (lane >> 4) * 16);
    uint32_t bRow  = (uint32_t)((lane >> 4) * 8 + (lane & 7));
    uint32_t bKoff = (uint32_t)(((lane >> 3) & 1) * 16);

    MMA_LOOP(c, aBase, sWu, bRow, bKoff);

    int r0 = row0 + warp * 16 + (lane >> 2);
    int r1 = r0 + 8;
    int q  = lane & 3;

    float rsi0 = (r0 < n) ? rs_in[r0] : 1.f;
    float rsi1 = (r1 < n) ? rs_in[r1] : 1.f;
    float s0 = 0.f, ss0 = 0.f, s1 = 0.f, ss1 = 0.f;
    #pragma unroll
    for (int ct = 0; ct < 16; ct++) {
        int colb = ct * 8 + q * 2;
        float bb0 = sBias[colb], bb1 = sBias[colb + 1];
        c[ct][0] = (c[ct][0] + bb0) * rsi0;
        c[ct][1] = (c[ct][1] + bb1) * rsi0;
        c[ct][2] = (c[ct][2] + bb0) * rsi1;
        c[ct][3] = (c[ct][3] + bb1) * rsi1;
        s0  += c[ct][0] + c[ct][1];
        ss0 += c[ct][0] * c[ct][0] + c[ct][1] * c[ct][1];
        s1  += c[ct][2] + c[ct][3];
        ss1 += c[ct][2] * c[ct][2] + c[ct][3] * c[ct][3];
    }
    #pragma unroll
    for (int o = 1; o <= 2; o <<= 1) {
        s0  += __shfl_xor_sync(0xffffffffu, s0,  o);
        ss0 += __shfl_xor_sync(0xffffffffu, ss0, o);
        s1  += __shfl_xor_sync(0xffffffffu, s1,  o);
        ss1 += __shfl_xor_sync(0xffffffffu, ss1, o);
    }
    float mu0 = s0 * (1.f / 128.f);
    float mu1 = s1 * (1.f / 128.f);
    float inv0 = rsqrtf(ss0 * (1.f / 128.f) - mu0 * mu0 + 1e-5f);
    float inv1 = rsqrtf(ss1 * (1.f / 128.f) - mu1 * mu1 + 1e-5f);
    float aP = alpha[0];
    float rso0 = (r0 < n) ? rs_out[r0] : 1.f;
    float rso1 = (r1 < n) ? rs_out[r1] : 1.f;
    #pragma unroll
    for (int ct = 0; ct < 16; ct++) {
        int colb = ct * 8 + q * 2;
        float g0 = sGamma[colb], g1 = sGamma[colb + 1];
        float e0 = sBeta[colb],  e1 = sBeta[colb + 1];
        float y0 = (c[ct][0] - mu0) * inv0 * g0 + e0; y0 = (y0 >= 0.f) ? y0 : aP * y0;
        float y1 = (c[ct][1] - mu0) * inv0 * g1 + e1; y1 = (y1 >= 0.f) ? y1 : aP * y1;
        float y2 = (c[ct][2] - mu1) * inv1 * g0 + e0; y2 = (y2 >= 0.f) ? y2 : aP * y2;
        float y3 = (c[ct][3] - mu1) * inv1 * g1 + e1; y3 = (y3 >= 0.f) ? y3 : aP * y3;
        int ci = ct * 4 + q;
        if (r0 < n) ((__half2*)outh)[(size_t)r0 * 64 + ci] = __floats2half2_rn(y0 * rso0, y1 * rso0);
        if (r1 < n) ((__half2*)outh)[(size_t)r1 * 64 + ci] = __floats2half2_rn(y2 * rso1, y3 * rso1);
    }
}

// ---------------- fused conv2-GEMM (LN+PReLU) + enc->dec-GEMM (re-mask, *rs_out) ----------
__global__ void __launch_bounds__(256, 2)
k_gemm_fused(const __half* __restrict__ in, __half* __restrict__ outS,
             const float* __restrict__ W2, const float* __restrict__ bias2,
             const float* __restrict__ We2d,
             const float* __restrict__ rs_in, const float* __restrict__ rs_out,
             const float* __restrict__ gamma, const float* __restrict__ beta,
             const float* __restrict__ alpha,
             const int* __restrict__ maskflag, int n) {
    extern __shared__ char smraw[];
    __half* sA = (__half*)smraw;
    __half* sW = sA + 128 * SROW;
    float* sBias  = (float*)(sW + 128 * SROW);
    float* sGamma = sBias + 128;
    float* sBeta  = sGamma + 128;

    const int tid  = threadIdx.x;
    const int row0 = blockIdx.x * 128;

    STAGE_A(in, sA, n);
    STAGE_W(W2, sW);
    if (tid < 128) { sBias[tid] = bias2[tid]; sGamma[tid] = gamma[tid]; sBeta[tid] = beta[tid]; }
    __syncthreads();

    const int warp = tid >> 5;
    const int lane = tid & 31;
    float c[16][4];
    #pragma unroll
    for (int i = 0; i < 16; i++) { c[i][0]=0.f; c[i][1]=0.f; c[i][2]=0.f; c[i][3]=0.f; }

    uint32_t sAu = (uint32_t)__cvta_generic_to_shared(sA);
    uint32_t sWu = (uint32_t)__cvta_generic_to_shared(sW);
    uint32_t aBase = sAu + (uint32_t)((warp * 16 + (lane & 15)) * (SROW * 2) + (lane >> 4) * 16);
    uint32_t bRow  = (uint32_t)((lane >> 4) * 8 + (lane & 7));
    uint32_t bKoff = (uint32_t)(((lane >> 3) & 1) * 16);

    MMA_LOOP(c, aBase, sWu, bRow, bKoff);

    int lr0 = warp * 16 + (lane >> 2);
    int lr1 = lr0 + 8;
    int r0 = row0 + lr0;
    int r1 = row0 + lr1;
    int q  = lane & 3;

    float rsi0 = (r0 < n) ? rs_in[r0] : 1.f;
    float rsi1 = (r1 < n) ? rs_in[r1] : 1.f;
    float s0 = 0.f, ss0 = 0.f, s1 = 0.f, ss1 = 0.f;
    #pragma unroll
    for (int ct = 0; ct < 16; ct++) {
        int colb = ct * 8 + q * 2;
        float bb0 = sBias[colb], bb1 = sBias[colb + 1];
        c[ct][0] = (c[ct][0] + bb0) * rsi0;
        c[ct][1] = (c[ct][1] + bb1) * rsi0;
        c[ct][2] = (c[ct][2] + bb0) * rsi1;
        c[ct][3] = (c[ct][3] + bb1) * rsi1;
        s0  += c[ct][0] + c[ct][1];
        ss0 += c[ct][0] * c[ct][0] + c[ct][1] * c[ct][1];
        s1  += c[ct][2] + c[ct][3];
        ss1 += c[ct][2] * c[ct][2] + c[ct][3] * c[ct][3];
    }
    #pragma unroll
    for (int o = 1; o <= 2; o <<= 1) {
        s0  += __shfl_xor_sync(0xffffffffu, s0,  o);
        ss0 += __shfl_xor_sync(0xffffffffu, ss0, o);
        s1  += __shfl_xor_sync(0xffffffffu, s1,  o);
        ss1 += __shfl_xor_sync(0xffffffffu, ss1, o);
    }
    float mu0 = s0 * (1.f / 128.f);
    float mu1 = s1 * (1.f / 128.f);
    float inv0 = rsqrtf(ss0 * (1.f / 128.f) - mu0 * mu0 + 1e-5f);
    float inv1 = rsqrtf(ss1 * (1.f / 128.f) - mu1 * mu1 + 1e-5f);
    float aP = alpha[0];
    #pragma unroll
    for (int ct = 0; ct < 16; ct++) {
        int colb = ct * 8 + q * 2;
        float g0 = sGamma[colb], g1 = sGamma[colb + 1];
        float e0 = sBeta[colb],  e1 = sBeta[colb + 1];
        float y0 = (c[ct][0] - mu0) * inv0 * g0 + e0; y0 = (y0 >= 0.f) ? y0 : aP * y0;
        float y1 = (c[ct][1] - mu0) * inv0 * g1 + e1; y1 = (y1 >= 0.f) ? y1 : aP * y1;
        float y2 = (c[ct][2] - mu1) * inv1 * g0 + e0; y2 = (y2 >= 0.f) ? y2 : aP * y2;
        float y3 = (c[ct][3] - mu1) * inv1 * g1 + e1; y3 = (y3 >= 0.f) ? y3 : aP * y3;
        *(__half2*)&sA[lr0 * SROW + colb] = __floats2half2_rn(y0, y1);
        *(__half2*)&sA[lr1 * SROW + colb] = __floats2half2_rn(y2, y3);
    }

    __syncthreads();
    STAGE_W(We2d, sW);
    __syncthreads();

    #pragma unroll
    for (int i = 0; i < 16; i++) { c[i][0]=0.f; c[i][1]=0.f; c[i][2]=0.f; c[i][3]=0.f; }
    MMA_LOOP(c, aBase, sWu, bRow, bKoff);

    float rso0 = (r0 < n) ? ((maskflag[r0]) ? 0.f : rs_out[r0]) : 0.f;
    float rso1 = (r1 < n) ? ((maskflag[r1]) ? 0.f : rs_out[r1]) : 0.f;
    #pragma unroll
    for (int ct = 0; ct < 16; ct++) {
        int ci = ct * 4 + q;
        if (r0 < n) ((__half2*)outS)[(size_t)r0 * 64 + ci] = __floats2half2_rn(c[ct][0] * rso0, c[ct][1] * rso0);
        if (r1 < n) ((__half2*)outS)[(size_t)r1 * 64 + ci] = __floats2half2_rn(c[ct][2] * rso1, c[ct][3] * rso1);
    }
}

// ---------------- decoder GEMM + fused SCE loss (compacted over m masked rows) ----------
// in = compacted agg rows (row j -> node mask_nodes[j]); computes recon row in registers,
// then cosine term vs x[node] via quad reduction; block-reduce; one atomicAdd per block.
__global__ void __launch_bounds__(256, 2)
k_gemm_loss(const __half* __restrict__ in, const float* __restrict__ x,
            const int* __restrict__ mask_nodes,
            const float* __restrict__ W, const float* __restrict__ bias,
            const float* __restrict__ rs_in,
            int m, float* __restrict__ out) {
    extern __shared__ char smraw[];
    __half* sA = (__half*)smraw;
    __half* sW = sA + 128 * SROW;
    float* sBias = (float*)(sW + 128 * SROW);
    float* sWsum = sBias + 128;     // [8] warp partial sums

    const int tid  = threadIdx.x;
    const int row0 = blockIdx.x * 128;

    STAGE_A(in, sA, m);
    STAGE_W(W, sW);
    if (tid < 128) sBias[tid] = bias[tid];
    __syncthreads();

    const int warp = tid >> 5;
    const int lane = tid & 31;
    float c[16][4];
    #pragma unroll
    for (int i = 0; i < 16; i++) { c[i][0]=0.f; c[i][1]=0.f; c[i][2]=0.f; c[i][3]=0.f; }

    uint32_t sAu = (uint32_t)__cvta_generic_to_shared(sA);
    uint32_t sWu = (uint32_t)__cvta_generic_to_shared(sW);
    uint32_t aBase = sAu + (uint32_t)((warp * 16 + (lane & 15)) * (SROW * 2) + (lane >> 4) * 16);
    uint32_t bRow  = (uint32_t)((lane >> 4) * 8 + (lane & 7));
    uint32_t bKoff = (uint32_t)(((lane >> 3) & 1) * 16);

    MMA_LOOP(c, aBase, sWu, bRow, bKoff);

    int r0 = row0 + warp * 16 + (lane >> 2);   // compacted row index
    int r1 = r0 + 8;
    int q  = lane & 3;

    int node0 = (r0 < m) ? mask_nodes[r0] : 0;
    int node1 = (r1 < m) ? mask_nodes[r1] : 0;
    float rsi0 = (r0 < m) ? rs_in[node0] : 0.f;
    float rsi1 = (r1 < m) ? rs_in[node1] : 0.f;

    float dot0 = 0.f, nr0 = 0.f, nx0 = 0.f;
    float dot1 = 0.f, nr1 = 0.f, nx1 = 0.f;
    const float* xp0 = x + (size_t)node0 * DD;
    const float* xp1 = x + (size_t)node1 * DD;
    #pragma unroll
    for (int ct = 0; ct < 16; ct++) {
        int colb = ct * 8 + q * 2;
        float bb0 = sBias[colb], bb1 = sBias[colb + 1];
        float v0 = (c[ct][0] + bb0) * rsi0;
        float v1 = (c[ct][1] + bb1) * rsi0;
        float v2 = (c[ct][2] + bb0) * rsi1;
        float v3 = (c[ct][3] + bb1) * rsi1;
        float xa0 = (r0 < m) ? xp0[colb]     : 0.f;
        float xa1 = (r0 < m) ? xp0[colb + 1] : 0.f;
        float xb0 = (r1 < m) ? xp1[colb]     : 0.f;
        float xb1 = (r1 < m) ? xp1[colb + 1] : 0.f;
        dot0 += v0 * xa0 + v1 * xa1;
        nr0  += v0 * v0 + v1 * v1;
        nx0  += xa0 * xa0 + xa1 * xa1;
        dot1 += v2 * xb0 + v3 * xb1;
        nr1  += v2 * v2 + v3 * v3;
        nx1  += xb0 * xb0 + xb1 * xb1;
    }
    #pragma unroll
    for (int o = 1; o <= 2; o <<= 1) {
        dot0 += __shfl_xor_sync(0xffffffffu, dot0, o);
        nr0  += __shfl_xor_sync(0xffffffffu, nr0,  o);
        nx0  += __shfl_xor_sync(0xffffffffu, nx0,  o);
        dot1 += __shfl_xor_sync(0xffffffffu, dot1, o);
        nr1  += __shfl_xor_sync(0xffffffffu, nr1,  o);
        nx1  += __shfl_xor_sync(0xffffffffu, nx1,  o);
    }
    float term = 0.f;
    if (q == 0) {
        if (r0 < m) {
            float cc = dot0 / (fmaxf(sqrtf(nr0), 1e-12f) * fmaxf(sqrtf(nx0), 1e-12f));
            float t = 1.f - cc;
            term += t * t;
        }
        if (r1 < m) {
            float cc = dot1 / (fmaxf(sqrtf(nr1), 1e-12f) * fmaxf(sqrtf(nx1), 1e-12f));
            float t = 1.f - cc;
            term += t * t;
        }
    }
    // reduce across quads in warp (q!=0 lanes hold 0)
    #pragma unroll
    for (int o = 4; o <= 16; o <<= 1) term += __shfl_xor_sync(0xffffffffu, term, o);
    if (lane == 0) sWsum[warp] = term;
    __syncthreads();
    if (tid == 0) {
        float s = 0.f;
        #pragma unroll
        for (int i = 0; i < 8; i++) s += sWsum[i];
        atomicAdd(out, s / (float)m);
    }
}

// ---------------- launch ----------------
extern "C" void kernel_launch(void* const* d_in, const int* in_sizes, int n_in,
                              void* d_out, int out_size) {
    const float* x     = (const float*)d_in[0];
    const float* token = (const float*)d_in[1];
    const float* W1    = (const float*)d_in[2];
    const float* b1    = (const float*)d_in[3];
    const float* g1    = (const float*)d_in[4];
    const float* be1   = (const float*)d_in[5];
    const float* a1    = (const float*)d_in[6];
    const float* W2    = (const float*)d_in[7];
    const float* b2    = (const float*)d_in[8];
    const float* g2    = (const float*)d_in[9];
    const float* be2   = (const float*)d_in[10];
    const float* a2    = (const float*)d_in[11];
    const float* We2d  = (const float*)d_in[12];
    const float* Wd    = (const float*)d_in[13];
    const float* bd    = (const float*)d_in[14];
    const int*   src   = (const int*)d_in[15];
    const int*   dst   = (const int*)d_in[16];
    const int*   mask  = (const int*)d_in[17];

    const int n = in_sizes[0] / DD;
    const int E = in_sizes[15];
    const int M = in_sizes[17];
    float* out = (float*)d_out;

    float *tokA, *rs_out, *rs_in;
    __half *S, *agg16;
    int *deg_out, *deg_in, *maskflag, *rowptr, *fill, *csrc;
    cudaGetSymbolAddress((void**)&S,     g_S);
    cudaGetSymbolAddress((void**)&agg16, g_agg16);
    cudaGetSymbolAddress((void**)&tokA,  g_token);
    cudaGetSymbolAddress((void**)&deg_out, g_deg_out);
    cudaGetSymbolAddress((void**)&deg_in,  g_deg_in);
    cudaGetSymbolAddress((void**)&rs_out, g_rs_out);
    cudaGetSymbolAddress((void**)&rs_in,  g_rs_in);
    cudaGetSymbolAddress((void**)&maskflag, g_maskflag);
    cudaGetSymbolAddress((void**)&rowptr, g_rowptr);
    cudaGetSymbolAddress((void**)&fill,   g_fill);
    cudaGetSymbolAddress((void**)&csrc,   g_csrc);

    const size_t smem = (size_t)(2 * 128 * SROW) * sizeof(__half) + 3 * 128 * sizeof(float);
    cudaFuncSetAttribute(k_gemm1, cudaFuncAttributeMaxDynamicSharedMemorySize, (int)smem);
    cudaFuncSetAttribute(k_gemm_fused, cudaFuncAttributeMaxDynamicSharedMemorySize, (int)smem);
    cudaFuncSetAttribute(k_gemm_loss, cudaFuncAttributeMaxDynamicSharedMemorySize, (int)smem);

    const int T = 256;
    const int gN = (n + T - 1) / T;
    const int gE = (E + T - 1) / T;
    const int gW = ((n * 32) + T - 1) / T;
    const int gWM = ((M * 32) + T - 1) / T;
    const int gG = (n + 127) / 128;
    const int gGM = (M + 127) / 128;

    // setup: 4 kernels
    k_init <<<gN, T>>>(token, tokA, deg_out, deg_in, fill, maskflag, out, n);
    k_deg  <<<gE, T>>>(src, dst, deg_out, deg_in, E);
    k_mid  <<<1, 1024>>>(mask, maskflag, M, deg_out, deg_in, rs_out, rs_in, rowptr, n);
    k_fill <<<gE, T>>>(src, dst, rowptr, fill, csrc, E);

    // conv1
    k_prep1<<<gW, T>>>(x, tokA, maskflag, rs_out, S, n);
    k_agg  <<<gW, T>>>(S, rowptr, csrc, agg16, n);
    k_gemm1<<<gG, 256, smem>>>(agg16, S, W1, b1, rs_in, rs_out, g1, be1, a1, n);

    // conv2 + enc->dec (fused)
    k_agg  <<<gW, T>>>(S, rowptr, csrc, agg16, n);
    k_gemm_fused<<<gG, 256, smem>>>(agg16, S, W2, b2, We2d, rs_in, rs_out, g2, be2, a2, maskflag, n);

    // decoder conv + loss (compacted over masked nodes)
    k_agg_dec<<<gWM, T>>>(S, rowptr, csrc, maskflag, mask, agg16, M);
    k_gemm_loss<<<gGM, 256, smem>>>(agg16, x, mask, Wd, bd, rs_in, M, out);
}

// round 12
// speedup vs baseline: 1.3095x; 1.3095x over previous
#include <cuda_runtime.h>
#include <cuda_fp16.h>
#include <cstdint>
#include <stdint.h>
#include <math.h>

#define DD 128
#define NMAX 50000
#define EMAX 800000
#define SROW 136            // smem row stride in halfs (272B, 16B-multiple)

// ---------------- scratch (static device globals) ----------------
__device__ __align__(16) __half g_S[(size_t)NMAX * DD];       // rs_out-scaled gather rows
__device__ __align__(16) __half g_agg16[(size_t)NMAX * DD];   // aggregation output (fp16)
__device__ __align__(16) float  g_token[DD];
__device__ int   g_deg_out[NMAX];
__device__ int   g_deg_in[NMAX];
__device__ float g_rs_out[NMAX];
__device__ float g_rs_in[NMAX];
__device__ int   g_maskflag[NMAX];
__device__ int   g_rowptr[NMAX + 1];
__device__ int   g_fill[NMAX];
__device__ int   g_bsum[128];
__device__ int   g_csrc[EMAX];

// ---------------- setup kernels ----------------
__global__ void k_init(const float* __restrict__ token, float* __restrict__ tok,
                       int* __restrict__ deg_out, int* __restrict__ deg_in,
                       int* __restrict__ fill, int* __restrict__ maskflag,
                       float* __restrict__ out, int n) {
    int i = blockIdx.x * blockDim.x + threadIdx.x;
    if (i < n) { deg_out[i] = 0; deg_in[i] = 0; fill[i] = 0; maskflag[i] = 0; }
    if (i < DD) tok[i] = token[i];
    if (i == 0) out[0] = 0.f;
}

__global__ void k_deg(const int* __restrict__ src, const int* __restrict__ dst,
                      int* __restrict__ dout, int* __restrict__ din, int e) {
    int i = blockIdx.x * blockDim.x + threadIdx.x;
    if (i < e) {
        atomicAdd(&dout[src[i]], 1);
        atomicAdd(&din[dst[i]], 1);
    }
}

__global__ void k_post(const int* __restrict__ mask_nodes, int* __restrict__ maskflag, int m,
                       const int* __restrict__ dout, const int* __restrict__ din,
                       float* __restrict__ ro, float* __restrict__ ri, int n) {
    int i = blockIdx.x * blockDim.x + threadIdx.x;
    if (i < n) {
        ro[i] = rsqrtf(fmaxf((float)dout[i], 1.f));
        ri[i] = rsqrtf(fmaxf((float)din[i], 1.f));
    }
    if (i < m) maskflag[mask_nodes[i]] = 1;
}

// ---------------- parallel exclusive scan (3 kernels) ----------------
__global__ void __launch_bounds__(1024)
k_scan1(const int* __restrict__ deg, int* __restrict__ rowptr,
        int* __restrict__ bsum, int n) {
    __shared__ int warpsum[32];
    int t = threadIdx.x;
    int gi = blockIdx.x * 1024 + t;
    int v = (gi < n) ? deg[gi] : 0;
    int lane = t & 31, wid = t >> 5;
    int inc = v;
    #pragma unroll
    for (int o = 1; o < 32; o <<= 1) {
        int u = __shfl_up_sync(0xffffffffu, inc, o);
        if (lane >= o) inc += u;
    }
    if (lane == 31) warpsum[wid] = inc;
    __syncthreads();
    if (wid == 0) {
        int w = warpsum[lane];
        #pragma unroll
        for (int o = 1; o < 32; o <<= 1) {
            int u = __shfl_up_sync(0xffffffffu, w, o);
            if (lane >= o) w += u;
        }
        warpsum[lane] = w;
    }
    __syncthreads();
    int woff = (wid > 0) ? warpsum[wid - 1] : 0;
    if (gi <= n) rowptr[gi] = woff + inc - v;
    if (t == 1023) bsum[blockIdx.x] = warpsum[31];
}

__global__ void k_scan2(int* __restrict__ bsum, int nb) {
    __shared__ int sm[128];
    int t = threadIdx.x;
    sm[t] = (t < nb) ? bsum[t] : 0;
    __syncthreads();
    #pragma unroll
    for (int o = 1; o < 128; o <<= 1) {
        int v = (t >= o) ? sm[t - o] : 0;
        __syncthreads();
        sm[t] += v;
        __syncthreads();
    }
    if (t < nb) bsum[t] = (t > 0) ? sm[t - 1] : 0;
}

__global__ void __launch_bounds__(1024)
k_scan3(int* __restrict__ rowptr, const int* __restrict__ bsum, int n) {
    int gi = blockIdx.x * 1024 + threadIdx.x;
    if (gi <= n) rowptr[gi] += bsum[blockIdx.x];
}

__global__ void k_fill(const int* __restrict__ src, const int* __restrict__ dst,
                       const int* __restrict__ rowptr, int* __restrict__ fill,
                       int* __restrict__ csrc, int e) {
    int i = blockIdx.x * blockDim.x + threadIdx.x;
    if (i < e) {
        int d = dst[i];
        int p = rowptr[d] + atomicAdd(&fill[d], 1);
        csrc[p] = src[i];
    }
}

// ---------------- prep: S[v] = (mask? token : x[v]) * rs_out[v] fp16 ----------------
__global__ void __launch_bounds__(256)
k_prep1(const float* __restrict__ x, const float* __restrict__ token,
        const int* __restrict__ maskflag, const float* __restrict__ rs_out,
        __half* __restrict__ S, int n) {
    int w = (blockIdx.x * blockDim.x + threadIdx.x) >> 5;
    int lane = threadIdx.x & 31;
    if (w >= n) return;
    float r = rs_out[w];
    const float* srcp = maskflag[w] ? (token + lane * 4) : (x + (size_t)w * DD + lane * 4);
    __half2 p0 = __floats2half2_rn(srcp[0] * r, srcp[1] * r);
    __half2 p1 = __floats2half2_rn(srcp[2] * r, srcp[3] * r);
    uint2 u;
    *(__half2*)&u.x = p0;
    *(__half2*)&u.y = p1;
    ((uint2*)S)[(size_t)w * 32 + lane] = u;
}

// ---------------- CSR aggregation (full) ----------------
__global__ void __launch_bounds__(256)
k_agg(const __half* __restrict__ S,
      const int* __restrict__ rowptr, const int* __restrict__ csrc,
      __half* __restrict__ agg, int n) {
    int w = (blockIdx.x * blockDim.x + threadIdx.x) >> 5;
    int lane = threadIdx.x & 31;
    if (w >= n) return;
    int beg = rowptr[w];
    int end = rowptr[w + 1];
    float4 acc = make_float4(0.f, 0.f, 0.f, 0.f);
    for (int e = beg; e < end; e++) {
        int s = csrc[e];
        uint2 u = ((const uint2*)S)[(size_t)s * 32 + lane];
        float2 f0 = __half22float2(*(__half2*)&u.x);
        float2 f1 = __half22float2(*(__half2*)&u.y);
        acc.x += f0.x; acc.y += f0.y; acc.z += f1.x; acc.w += f1.y;
    }
    uint2 o;
    *(__half2*)&o.x = __floats2half2_rn(acc.x, acc.y);
    *(__half2*)&o.y = __floats2half2_rn(acc.z, acc.w);
    ((uint2*)agg)[(size_t)w * 32 + lane] = o;
}

// ---------------- decoder aggregation (compacted over mask_nodes) ----------------
__global__ void __launch_bounds__(256)
k_agg_dec(const __half* __restrict__ S,
          const int* __restrict__ rowptr, const int* __restrict__ csrc,
          const int* __restrict__ maskflag, const int* __restrict__ mask_nodes,
          __half* __restrict__ agg, int m) {
    int j = (blockIdx.x * blockDim.x + threadIdx.x) >> 5;
    int lane = threadIdx.x & 31;
    if (j >= m) return;
    int node = mask_nodes[j];
    int beg = rowptr[node];
    int end = rowptr[node + 1];
    float4 acc = make_float4(0.f, 0.f, 0.f, 0.f);
    for (int e = beg; e < end; e++) {
        int s = csrc[e];
        if (maskflag[s]) continue;        // re-masked row is zero
        uint2 u = ((const uint2*)S)[(size_t)s * 32 + lane];
        float2 f0 = __half22float2(*(__half2*)&u.x);
        float2 f1 = __half22float2(*(__half2*)&u.y);
        acc.x += f0.x; acc.y += f0.y; acc.z += f1.x; acc.w += f1.y;
    }
    uint2 o;
    *(__half2*)&o.x = __floats2half2_rn(acc.x, acc.y);
    *(__half2*)&o.y = __floats2half2_rn(acc.z, acc.w);
    ((uint2*)agg)[(size_t)j * 32 + lane] = o;
}

// ---------------- mma helper macros ----------------
#define MMA_LOOP(cacc, aBase, sWu, bRow, bKoff)                                              \
    _Pragma("unroll")                                                                         \
    for (int kb = 0; kb < 8; kb++) {                                                          \
        uint32_t a0, a1, a2, a3;                                                              \
        asm volatile("ldmatrix.sync.aligned.m8n8.x4.shared.b16 {%0,%1,%2,%3}, [%4];"         \
                     : "=r"(a0), "=r"(a1), "=r"(a2), "=r"(a3)                                 \
                     : "r"((aBase) + kb * 32));                                               \
        _Pragma("unroll")                                                                     \
        for (int ng = 0; ng < 8; ng++) {                                                      \
            uint32_t b0, b1, b2, b3;                                                          \
            uint32_t baddr = (sWu) + (uint32_t)((ng * 16 + (bRow)) * (SROW * 2) + kb * 32 + (bKoff)); \
            asm volatile("ldmatrix.sync.aligned.m8n8.x4.shared.b16 {%0,%1,%2,%3}, [%4];"     \
                         : "=r"(b0), "=r"(b1), "=r"(b2), "=r"(b3)                             \
                         : "r"(baddr));                                                       \
            int t0 = ng * 2, t1 = ng * 2 + 1;                                                 \
            asm volatile("mma.sync.aligned.m16n8k16.row.col.f32.f16.f16.f32 "                \
                         "{%0,%1,%2,%3}, {%4,%5,%6,%7}, {%8,%9}, {%0,%1,%2,%3};"             \
                         : "+f"(cacc[t0][0]), "+f"(cacc[t0][1]), "+f"(cacc[t0][2]), "+f"(cacc[t0][3]) \
                         : "r"(a0), "r"(a1), "r"(a2), "r"(a3), "r"(b0), "r"(b1));             \
            asm volatile("mma.sync.aligned.m16n8k16.row.col.f32.f16.f16.f32 "                \
                         "{%0,%1,%2,%3}, {%4,%5,%6,%7}, {%8,%9}, {%0,%1,%2,%3};"             \
                         : "+f"(cacc[t1][0]), "+f"(cacc[t1][1]), "+f"(cacc[t1][2]), "+f"(cacc[t1][3]) \
                         : "r"(a0), "r"(a1), "r"(a2), "r"(a3), "r"(b2), "r"(b3));             \
        }                                                                                     \
    }

#define STAGE_W(Wp, sW)                                                                       \
    _Pragma("unroll")                                                                         \
    for (int it = 0; it < 32; it++) {                                                         \
        int idx = it * 256 + threadIdx.x;                                                     \
        int base2 = idx * 2;                                                                  \
        int cc = base2 >> 7, kk = base2 & 127;                                                \
        float w0 = (Wp)[base2], w1 = (Wp)[base2 + 1];                                         \
        *(__half2*)&(sW)[cc * SROW + kk] = __floats2half2_rn(w0, w1);                         \
    }

#define STAGE_A(inp, sA, nrows)                                                               \
    _Pragma("unroll")                                                                         \
    for (int it = 0; it < 8; it++) {                                                          \
        int idx = it * 256 + threadIdx.x;                                                     \
        int r = idx >> 4, c8 = idx & 15;                                                      \
        uint4 v = make_uint4(0u, 0u, 0u, 0u);                                                 \
        int gr = row0 + r;                                                                    \
        if (gr < (nrows)) v = ((const uint4*)(inp))[(size_t)gr * 16 + c8];                    \
        *(uint4*)&(sA)[r * SROW + c8 * 8] = v;                                                \
    }

// ---------------- conv1 GEMM: (acc+b)*rs_in -> LN -> PReLU -> fp16 *rs_out -> S ----------
__global__ void __launch_bounds__(256, 2)
k_gemm1(const __half* __restrict__ in, __half* __restrict__ outh,
        const float* __restrict__ W, const float* __restrict__ bias,
        const float* __restrict__ rs_in, const float* __restrict__ rs_out,
        const float* __restrict__ gamma, const float* __restrict__ beta,
        const float* __restrict__ alpha, int n) {
    extern __shared__ char smraw[];
    __half* sA = (__half*)smraw;
    __half* sW = sA + 128 * SROW;
    float* sBias  = (float*)(sW + 128 * SROW);
    float* sGamma = sBias + 128;
    float* sBeta  = sGamma + 128;

    const int tid  = threadIdx.x;
    const int row0 = blockIdx.x * 128;

    STAGE_A(in, sA, n);
    STAGE_W(W, sW);
    if (tid < 128) { sBias[tid] = bias[tid]; sGamma[tid] = gamma[tid]; sBeta[tid] = beta[tid]; }
    __syncthreads();

    const int warp = tid >> 5;
    const int lane = tid & 31;
    float c[16][4];
    #pragma unroll
    for (int i = 0; i < 16; i++) { c[i][0]=0.f; c[i][1]=0.f; c[i][2]=0.f; c[i][3]=0.f; }

    uint32_t sAu = (uint32_t)__cvta_generic_to_shared(sA);
    uint32_t sWu = (uint32_t)__cvta_generic_to_shared(sW);
    uint32_t aBase = sAu + (uint32_t)((warp * 16 + (lane & 15)) * (SROW * 2) + (lane >> 4) * 16);
    uint32_t bRow  = (uint32_t)((lane >> 4) * 8 + (lane & 7));
    uint32_t bKoff = (uint32_t)(((lane >> 3) & 1) * 16);

    MMA_LOOP(c, aBase, sWu, bRow, bKoff);

    int r0 = row0 + warp * 16 + (lane >> 2);
    int r1 = r0 + 8;
    int q  = lane & 3;

    float rsi0 = (r0 < n) ? rs_in[r0] : 1.f;
    float rsi1 = (r1 < n) ? rs_in[r1] : 1.f;
    float s0 = 0.f, ss0 = 0.f, s1 = 0.f, ss1 = 0.f;
    #pragma unroll
    for (int ct = 0; ct < 16; ct++) {
        int colb = ct * 8 + q * 2;
        float bb0 = sBias[colb], bb1 = sBias[colb + 1];
        c[ct][0] = (c[ct][0] + bb0) * rsi0;
        c[ct][1] = (c[ct][1] + bb1) * rsi0;
        c[ct][2] = (c[ct][2] + bb0) * rsi1;
        c[ct][3] = (c[ct][3] + bb1) * rsi1;
        s0  += c[ct][0] + c[ct][1];
        ss0 += c[ct][0] * c[ct][0] + c[ct][1] * c[ct][1];
        s1  += c[ct][2] + c[ct][3];
        ss1 += c[ct][2] * c[ct][2] + c[ct][3] * c[ct][3];
    }
    #pragma unroll
    for (int o = 1; o <= 2; o <<= 1) {
        s0  += __shfl_xor_sync(0xffffffffu, s0,  o);
        ss0 += __shfl_xor_sync(0xffffffffu, ss0, o);
        s1  += __shfl_xor_sync(0xffffffffu, s1,  o);
        ss1 += __shfl_xor_sync(0xffffffffu, ss1, o);
    }
    float mu0 = s0 * (1.f / 128.f);
    float mu1 = s1 * (1.f / 128.f);
    float inv0 = rsqrtf(ss0 * (1.f / 128.f) - mu0 * mu0 + 1e-5f);
    float inv1 = rsqrtf(ss1 * (1.f / 128.f) - mu1 * mu1 + 1e-5f);
    float aP = alpha[0];
    float rso0 = (r0 < n) ? rs_out[r0] : 1.f;
    float rso1 = (r1 < n) ? rs_out[r1] : 1.f;
    #pragma unroll
    for (int ct = 0; ct < 16; ct++) {
        int colb = ct * 8 + q * 2;
        float g0 = sGamma[colb], g1 = sGamma[colb + 1];
        float e0 = sBeta[colb],  e1 = sBeta[colb + 1];
        float y0 = (c[ct][0] - mu0) * inv0 * g0 + e0; y0 = (y0 >= 0.f) ? y0 : aP * y0;
        float y1 = (c[ct][1] - mu0) * inv0 * g1 + e1; y1 = (y1 >= 0.f) ? y1 : aP * y1;
        float y2 = (c[ct][2] - mu1) * inv1 * g0 + e0; y2 = (y2 >= 0.f) ? y2 : aP * y2;
        float y3 = (c[ct][3] - mu1) * inv1 * g1 + e1; y3 = (y3 >= 0.f) ? y3 : aP * y3;
        int ci = ct * 4 + q;
        if (r0 < n) ((__half2*)outh)[(size_t)r0 * 64 + ci] = __floats2half2_rn(y0 * rso0, y1 * rso0);
        if (r1 < n) ((__half2*)outh)[(size_t)r1 * 64 + ci] = __floats2half2_rn(y2 * rso1, y3 * rso1);
    }
}

// ---------------- fused conv2-GEMM (LN+PReLU) + enc->dec-GEMM (re-mask, *rs_out) ----------
__global__ void __launch_bounds__(256, 2)
k_gemm_fused(const __half* __restrict__ in, __half* __restrict__ outS,
             const float* __restrict__ W2, const float* __restrict__ bias2,
             const float* __restrict__ We2d,
             const float* __restrict__ rs_in, const float* __restrict__ rs_out,
             const float* __restrict__ gamma, const float* __restrict__ beta,
             const float* __restrict__ alpha,
             const int* __restrict__ maskflag, int n) {
    extern __shared__ char smraw[];
    __half* sA = (__half*)smraw;
    __half* sW = sA + 128 * SROW;
    float* sBias  = (float*)(sW + 128 * SROW);
    float* sGamma = sBias + 128;
    float* sBeta  = sGamma + 128;

    const int tid  = threadIdx.x;
    const int row0 = blockIdx.x * 128;

    STAGE_A(in, sA, n);
    STAGE_W(W2, sW);
    if (tid < 128) { sBias[tid] = bias2[tid]; sGamma[tid] = gamma[tid]; sBeta[tid] = beta[tid]; }
    __syncthreads();

    const int warp = tid >> 5;
    const int lane = tid & 31;
    float c[16][4];
    #pragma unroll
    for (int i = 0; i < 16; i++) { c[i][0]=0.f; c[i][1]=0.f; c[i][2]=0.f; c[i][3]=0.f; }

    uint32_t sAu = (uint32_t)__cvta_generic_to_shared(sA);
    uint32_t sWu = (uint32_t)__cvta_generic_to_shared(sW);
    uint32_t aBase = sAu + (uint32_t)((warp * 16 + (lane & 15)) * (SROW * 2) + (lane >> 4) * 16);
    uint32_t bRow  = (uint32_t)((lane >> 4) * 8 + (lane & 7));
    uint32_t bKoff = (uint32_t)(((lane >> 3) & 1) * 16);

    MMA_LOOP(c, aBase, sWu, bRow, bKoff);

    int lr0 = warp * 16 + (lane >> 2);
    int lr1 = lr0 + 8;
    int r0 = row0 + lr0;
    int r1 = row0 + lr1;
    int q  = lane & 3;

    float rsi0 = (r0 < n) ? rs_in[r0] : 1.f;
    float rsi1 = (r1 < n) ? rs_in[r1] : 1.f;
    float s0 = 0.f, ss0 = 0.f, s1 = 0.f, ss1 = 0.f;
    #pragma unroll
    for (int ct = 0; ct < 16; ct++) {
        int colb = ct * 8 + q * 2;
        float bb0 = sBias[colb], bb1 = sBias[colb + 1];
        c[ct][0] = (c[ct][0] + bb0) * rsi0;
        c[ct][1] = (c[ct][1] + bb1) * rsi0;
        c[ct][2] = (c[ct][2] + bb0) * rsi1;
        c[ct][3] = (c[ct][3] + bb1) * rsi1;
        s0  += c[ct][0] + c[ct][1];
        ss0 += c[ct][0] * c[ct][0] + c[ct][1] * c[ct][1];
        s1  += c[ct][2] + c[ct][3];
        ss1 += c[ct][2] * c[ct][2] + c[ct][3] * c[ct][3];
    }
    #pragma unroll
    for (int o = 1; o <= 2; o <<= 1) {
        s0  += __shfl_xor_sync(0xffffffffu, s0,  o);
        ss0 += __shfl_xor_sync(0xffffffffu, ss0, o);
        s1  += __shfl_xor_sync(0xffffffffu, s1,  o);
        ss1 += __shfl_xor_sync(0xffffffffu, ss1, o);
    }
    float mu0 = s0 * (1.f / 128.f);
    float mu1 = s1 * (1.f / 128.f);
    float inv0 = rsqrtf(ss0 * (1.f / 128.f) - mu0 * mu0 + 1e-5f);
    float inv1 = rsqrtf(ss1 * (1.f / 128.f) - mu1 * mu1 + 1e-5f);
    float aP = alpha[0];
    #pragma unroll
    for (int ct = 0; ct < 16; ct++) {
        int colb = ct * 8 + q * 2;
        float g0 = sGamma[colb], g1 = sGamma[colb + 1];
        float e0 = sBeta[colb],  e1 = sBeta[colb + 1];
        float y0 = (c[ct][0] - mu0) * inv0 * g0 + e0; y0 = (y0 >= 0.f) ? y0 : aP * y0;
        float y1 = (c[ct][1] - mu0) * inv0 * g1 + e1; y1 = (y1 >= 0.f) ? y1 : aP * y1;
        float y2 = (c[ct][2] - mu1) * inv1 * g0 + e0; y2 = (y2 >= 0.f) ? y2 : aP * y2;
        float y3 = (c[ct][3] - mu1) * inv1 * g1 + e1; y3 = (y3 >= 0.f) ? y3 : aP * y3;
        *(__half2*)&sA[lr0 * SROW + colb] = __floats2half2_rn(y0, y1);
        *(__half2*)&sA[lr1 * SROW + colb] = __floats2half2_rn(y2, y3);
    }

    __syncthreads();
    STAGE_W(We2d, sW);
    __syncthreads();

    #pragma unroll
    for (int i = 0; i < 16; i++) { c[i][0]=0.f; c[i][1]=0.f; c[i][2]=0.f; c[i][3]=0.f; }
    MMA_LOOP(c, aBase, sWu, bRow, bKoff);

    float rso0 = (r0 < n) ? ((maskflag[r0]) ? 0.f : rs_out[r0]) : 0.f;
    float rso1 = (r1 < n) ? ((maskflag[r1]) ? 0.f : rs_out[r1]) : 0.f;
    #pragma unroll
    for (int ct = 0; ct < 16; ct++) {
        int ci = ct * 4 + q;
        if (r0 < n) ((__half2*)outS)[(size_t)r0 * 64 + ci] = __floats2half2_rn(c[ct][0] * rso0, c[ct][1] * rso0);
        if (r1 < n) ((__half2*)outS)[(size_t)r1 * 64 + ci] = __floats2half2_rn(c[ct][2] * rso1, c[ct][3] * rso1);
    }
}

// ---------------- decoder GEMM + fused SCE loss (compacted over m masked rows) ----------
__global__ void __launch_bounds__(256, 2)
k_gemm_loss(const __half* __restrict__ in, const float* __restrict__ x,
            const int* __restrict__ mask_nodes,
            const float* __restrict__ W, const float* __restrict__ bias,
            const float* __restrict__ rs_in,
            int m, float* __restrict__ out) {
    extern __shared__ char smraw[];
    __half* sA = (__half*)smraw;
    __half* sW = sA + 128 * SROW;
    float* sBias = (float*)(sW + 128 * SROW);
    float* sWsum = sBias + 128;     // [8] warp partial sums

    const int tid  = threadIdx.x;
    const int row0 = blockIdx.x * 128;

    STAGE_A(in, sA, m);
    STAGE_W(W, sW);
    if (tid < 128) sBias[tid] = bias[tid];
    __syncthreads();

    const int warp = tid >> 5;
    const int lane = tid & 31;
    float c[16][4];
    #pragma unroll
    for (int i = 0; i < 16; i++) { c[i][0]=0.f; c[i][1]=0.f; c[i][2]=0.f; c[i][3]=0.f; }

    uint32_t sAu = (uint32_t)__cvta_generic_to_shared(sA);
    uint32_t sWu = (uint32_t)__cvta_generic_to_shared(sW);
    uint32_t aBase = sAu + (uint32_t)((warp * 16 + (lane & 15)) * (SROW * 2) + (lane >> 4) * 16);
    uint32_t bRow  = (uint32_t)((lane >> 4) * 8 + (lane & 7));
    uint32_t bKoff = (uint32_t)(((lane >> 3) & 1) * 16);

    MMA_LOOP(c, aBase, sWu, bRow, bKoff);

    int r0 = row0 + warp * 16 + (lane >> 2);   // compacted row index
    int r1 = r0 + 8;
    int q  = lane & 3;

    int node0 = (r0 < m) ? mask_nodes[r0] : 0;
    int node1 = (r1 < m) ? mask_nodes[r1] : 0;
    float rsi0 = (r0 < m) ? rs_in[node0] : 0.f;
    float rsi1 = (r1 < m) ? rs_in[node1] : 0.f;

    float dot0 = 0.f, nr0 = 0.f, nx0 = 0.f;
    float dot1 = 0.f, nr1 = 0.f, nx1 = 0.f;
    const float* xp0 = x + (size_t)node0 * DD;
    const float* xp1 = x + (size_t)node1 * DD;
    #pragma unroll
    for (int ct = 0; ct < 16; ct++) {
        int colb = ct * 8 + q * 2;
        float bb0 = sBias[colb], bb1 = sBias[colb + 1];
        float v0 = (c[ct][0] + bb0) * rsi0;
        float v1 = (c[ct][1] + bb1) * rsi0;
        float v2 = (c[ct][2] + bb0) * rsi1;
        float v3 = (c[ct][3] + bb1) * rsi1;
        float xa0 = (r0 < m) ? xp0[colb]     : 0.f;
        float xa1 = (r0 < m) ? xp0[colb + 1] : 0.f;
        float xb0 = (r1 < m) ? xp1[colb]     : 0.f;
        float xb1 = (r1 < m) ? xp1[colb + 1] : 0.f;
        dot0 += v0 * xa0 + v1 * xa1;
        nr0  += v0 * v0 + v1 * v1;
        nx0  += xa0 * xa0 + xa1 * xa1;
        dot1 += v2 * xb0 + v3 * xb1;
        nr1  += v2 * v2 + v3 * v3;
        nx1  += xb0 * xb0 + xb1 * xb1;
    }
    #pragma unroll
    for (int o = 1; o <= 2; o <<= 1) {
        dot0 += __shfl_xor_sync(0xffffffffu, dot0, o);
        nr0  += __shfl_xor_sync(0xffffffffu, nr0,  o);
        nx0  += __shfl_xor_sync(0xffffffffu, nx0,  o);
        dot1 += __shfl_xor_sync(0xffffffffu, dot1, o);
        nr1  += __shfl_xor_sync(0xffffffffu, nr1,  o);
        nx1  += __shfl_xor_sync(0xffffffffu, nx1,  o);
    }
    float term = 0.f;
    if (q == 0) {
        if (r0 < m) {
            float cc = dot0 / (fmaxf(sqrtf(nr0), 1e-12f) * fmaxf(sqrtf(nx0), 1e-12f));
            float t = 1.f - cc;
            term += t * t;
        }
        if (r1 < m) {
            float cc = dot1 / (fmaxf(sqrtf(nr1), 1e-12f) * fmaxf(sqrtf(nx1), 1e-12f));
            float t = 1.f - cc;
            term += t * t;
        }
    }
    #pragma unroll
    for (int o = 4; o <= 16; o <<= 1) term += __shfl_xor_sync(0xffffffffu, term, o);
    if (lane == 0) sWsum[warp] = term;
    __syncthreads();
    if (tid == 0) {
        float s = 0.f;
        #pragma unroll
        for (int i = 0; i < 8; i++) s += sWsum[i];
        atomicAdd(out, s / (float)m);
    }
}

// ---------------- launch ----------------
extern "C" void kernel_launch(void* const* d_in, const int* in_sizes, int n_in,
                              void* d_out, int out_size) {
    const float* x     = (const float*)d_in[0];
    const float* token = (const float*)d_in[1];
    const float* W1    = (const float*)d_in[2];
    const float* b1    = (const float*)d_in[3];
    const float* g1    = (const float*)d_in[4];
    const float* be1   = (const float*)d_in[5];
    const float* a1    = (const float*)d_in[6];
    const float* W2    = (const float*)d_in[7];
    const float* b2    = (const float*)d_in[8];
    const float* g2    = (const float*)d_in[9];
    const float* be2   = (const float*)d_in[10];
    const float* a2    = (const float*)d_in[11];
    const float* We2d  = (const float*)d_in[12];
    const float* Wd    = (const float*)d_in[13];
    const float* bd    = (const float*)d_in[14];
    const int*   src   = (const int*)d_in[15];
    const int*   dst   = (const int*)d_in[16];
    const int*   mask  = (const int*)d_in[17];

    const int n = in_sizes[0] / DD;
    const int E = in_sizes[15];
    const int M = in_sizes[17];
    float* out = (float*)d_out;

    float *tokA, *rs_out, *rs_in;
    __half *S, *agg16;
    int *deg_out, *deg_in, *maskflag, *rowptr, *fill, *csrc, *bsum;
    cudaGetSymbolAddress((void**)&S,     g_S);
    cudaGetSymbolAddress((void**)&agg16, g_agg16);
    cudaGetSymbolAddress((void**)&tokA,  g_token);
    cudaGetSymbolAddress((void**)&deg_out, g_deg_out);
    cudaGetSymbolAddress((void**)&deg_in,  g_deg_in);
    cudaGetSymbolAddress((void**)&rs_out, g_rs_out);
    cudaGetSymbolAddress((void**)&rs_in,  g_rs_in);
    cudaGetSymbolAddress((void**)&maskflag, g_maskflag);
    cudaGetSymbolAddress((void**)&rowptr, g_rowptr);
    cudaGetSymbolAddress((void**)&fill,   g_fill);
    cudaGetSymbolAddress((void**)&csrc,   g_csrc);
    cudaGetSymbolAddress((void**)&bsum,   g_bsum);

    const size_t smem = (size_t)(2 * 128 * SROW) * sizeof(__half) + 3 * 128 * sizeof(float);
    cudaFuncSetAttribute(k_gemm1, cudaFuncAttributeMaxDynamicSharedMemorySize, (int)smem);
    cudaFuncSetAttribute(k_gemm_fused, cudaFuncAttributeMaxDynamicSharedMemorySize, (int)smem);
    cudaFuncSetAttribute(k_gemm_loss, cudaFuncAttributeMaxDynamicSharedMemorySize, (int)smem);

    const int T = 256;
    const int gN = (n + T - 1) / T;
    const int gE = (E + T - 1) / T;
    const int gW = ((n * 32) + T - 1) / T;
    const int gWM = ((M * 32) + T - 1) / T;
    const int gG = (n + 127) / 128;
    const int gGM = (M + 127) / 128;
    const int nb = (n + 1 + 1023) / 1024;

    // setup (parallel versions)
    k_init <<<gN, T>>>(token, tokA, deg_out, deg_in, fill, maskflag, out, n);
    k_deg  <<<gE, T>>>(src, dst, deg_out, deg_in, E);
    k_post <<<gN, T>>>(mask, maskflag, M, deg_out, deg_in, rs_out, rs_in, n);
    k_scan1<<<nb, 1024>>>(deg_in, rowptr, bsum, n);
    k_scan2<<<1, 128>>>(bsum, nb);
    k_scan3<<<nb, 1024>>>(rowptr, bsum, n);
    k_fill <<<gE, T>>>(src, dst, rowptr, fill, csrc, E);

    // conv1
    k_prep1<<<gW, T>>>(x, tokA, maskflag, rs_out, S, n);
    k_agg  <<<gW, T>>>(S, rowptr, csrc, agg16, n);
    k_gemm1<<<gG, 256, smem>>>(agg16, S, W1, b1, rs_in, rs_out, g1, be1, a1, n);

    // conv2 + enc->dec (fused)
    k_agg  <<<gW, T>>>(S, rowptr, csrc, agg16, n);
    k_gemm_fused<<<gG, 256, smem>>>(agg16, S, W2, b2, We2d, rs_in, rs_out, g2, be2, a2, maskflag, n);

    // decoder conv + loss (compacted over masked nodes)
    k_agg_dec<<<gWM, T>>>(S, rowptr, csrc, maskflag, mask, agg16, M);
    k_gemm_loss<<<gGM, 256, smem>>>(agg16, x, mask, Wd, bd, rs_in, M, out);
}

// round 13
// speedup vs baseline: 1.4361x; 1.0967x over previous
#include <cuda_runtime.h>
#include <cuda_fp16.h>
#include <cstdint>
#include <stdint.h>
#include <math.h>

#define DD 128
#define NMAX 50000
#define EMAX 800000
#define SROW 136            // smem row stride in halfs (272B, 16B-multiple)

// ---------------- scratch (static device globals) ----------------
__device__ __align__(16) __half g_S[(size_t)NMAX * DD];       // rs_out-scaled gather rows
__device__ __align__(16) __half g_agg16[(size_t)NMAX * DD];   // aggregation output (fp16)
__device__ __align__(16) float  g_token[DD];
__device__ int   g_deg_out[NMAX];
__device__ int   g_deg_in[NMAX];
__device__ float g_rs_out[NMAX];
__device__ float g_rs_in[NMAX];
__device__ int   g_maskflag[NMAX];
__device__ int   g_rowptr[NMAX + 1];
__device__ int   g_fill[NMAX];
__device__ int   g_bsum[128];
__device__ int   g_nonmask[NMAX];
__device__ int   g_nmcount;
__device__ int   g_csrc[EMAX];

// ---------------- setup kernels ----------------
__global__ void k_init(const float* __restrict__ token, float* __restrict__ tok,
                       int* __restrict__ deg_out, int* __restrict__ deg_in,
                       int* __restrict__ fill, int* __restrict__ maskflag,
                       int* __restrict__ nmcount,
                       float* __restrict__ out, int n) {
    int i = blockIdx.x * blockDim.x + threadIdx.x;
    if (i < n) { deg_out[i] = 0; deg_in[i] = 0; fill[i] = 0; maskflag[i] = 0; }
    if (i < DD) tok[i] = token[i];
    if (i == 0) { out[0] = 0.f; *nmcount = 0; }
}

__global__ void k_deg(const int* __restrict__ src, const int* __restrict__ dst,
                      int* __restrict__ dout, int* __restrict__ din, int e) {
    int i = blockIdx.x * blockDim.x + threadIdx.x;
    if (i < e) {
        atomicAdd(&dout[src[i]], 1);
        atomicAdd(&din[dst[i]], 1);
    }
}

__global__ void k_post(const int* __restrict__ mask_nodes, int* __restrict__ maskflag, int m,
                       const int* __restrict__ dout, const int* __restrict__ din,
                       float* __restrict__ ro, float* __restrict__ ri, int n) {
    int i = blockIdx.x * blockDim.x + threadIdx.x;
    if (i < n) {
        ro[i] = rsqrtf(fmaxf((float)dout[i], 1.f));
        ri[i] = rsqrtf(fmaxf((float)din[i], 1.f));
    }
    if (i < m) maskflag[mask_nodes[i]] = 1;
}

// ---------------- parallel exclusive scan (2 kernels) ----------------
__global__ void __launch_bounds__(1024)
k_scan1(const int* __restrict__ deg, int* __restrict__ rowptr,
        int* __restrict__ bsum, int n) {
    __shared__ int warpsum[32];
    int t = threadIdx.x;
    int gi = blockIdx.x * 1024 + t;
    int v = (gi < n) ? deg[gi] : 0;
    int lane = t & 31, wid = t >> 5;
    int inc = v;
    #pragma unroll
    for (int o = 1; o < 32; o <<= 1) {
        int u = __shfl_up_sync(0xffffffffu, inc, o);
        if (lane >= o) inc += u;
    }
    if (lane == 31) warpsum[wid] = inc;
    __syncthreads();
    if (wid == 0) {
        int w = warpsum[lane];
        #pragma unroll
        for (int o = 1; o < 32; o <<= 1) {
            int u = __shfl_up_sync(0xffffffffu, w, o);
            if (lane >= o) w += u;
        }
        warpsum[lane] = w;
    }
    __syncthreads();
    int woff = (wid > 0) ? warpsum[wid - 1] : 0;
    if (gi <= n) rowptr[gi] = woff + inc - v;
    if (t == 1023) bsum[blockIdx.x] = warpsum[31];
}

// add block offsets (computed in-block from raw bsum) + build nonmask list
__global__ void __launch_bounds__(1024)
k_scan3(int* __restrict__ rowptr, const int* __restrict__ bsum,
        const int* __restrict__ maskflag, int* __restrict__ nonmask,
        int* __restrict__ nmcount, int n) {
    __shared__ int soff;
    int t = threadIdx.x;
    if (t < 32) {
        int ssum = 0;
        for (int i = t; i < blockIdx.x; i += 32) ssum += bsum[i];
        #pragma unroll
        for (int o = 16; o; o >>= 1) ssum += __shfl_xor_sync(0xffffffffu, ssum, o);
        if (t == 0) soff = ssum;
    }
    __syncthreads();
    int gi = blockIdx.x * 1024 + t;
    if (gi <= n) rowptr[gi] += soff;
    if (gi < n && !maskflag[gi]) {
        int p = atomicAdd(nmcount, 1);
        nonmask[p] = gi;
    }
}

__global__ void k_fill(const int* __restrict__ src, const int* __restrict__ dst,
                       const int* __restrict__ rowptr, int* __restrict__ fill,
                       int* __restrict__ csrc, int e) {
    int i = blockIdx.x * blockDim.x + threadIdx.x;
    if (i < e) {
        int d = dst[i];
        int p = rowptr[d] + atomicAdd(&fill[d], 1);
        csrc[p] = src[i];
    }
}

// ---------------- prep: S[v] = (mask? token : x[v]) * rs_out[v] fp16 ----------------
__global__ void __launch_bounds__(256)
k_prep1(const float* __restrict__ x, const float* __restrict__ token,
        const int* __restrict__ maskflag, const float* __restrict__ rs_out,
        __half* __restrict__ S, int n) {
    int w = (blockIdx.x * blockDim.x + threadIdx.x) >> 5;
    int lane = threadIdx.x & 31;
    if (w >= n) return;
    float r = rs_out[w];
    const float* srcp = maskflag[w] ? (token + lane * 4) : (x + (size_t)w * DD + lane * 4);
    __half2 p0 = __floats2half2_rn(srcp[0] * r, srcp[1] * r);
    __half2 p1 = __floats2half2_rn(srcp[2] * r, srcp[3] * r);
    uint2 u;
    *(__half2*)&u.x = p0;
    *(__half2*)&u.y = p1;
    ((uint2*)S)[(size_t)w * 32 + lane] = u;
}

// ---------------- CSR aggregation over all nodes ----------------
__global__ void __launch_bounds__(256)
k_agg(const __half* __restrict__ S,
      const int* __restrict__ rowptr, const int* __restrict__ csrc,
      __half* __restrict__ agg, int n) {
    int w = (blockIdx.x * blockDim.x + threadIdx.x) >> 5;
    int lane = threadIdx.x & 31;
    if (w >= n) return;
    int beg = rowptr[w];
    int end = rowptr[w + 1];
    float4 acc = make_float4(0.f, 0.f, 0.f, 0.f);
    for (int e = beg; e < end; e++) {
        int s = csrc[e];
        uint2 u = ((const uint2*)S)[(size_t)s * 32 + lane];
        float2 f0 = __half22float2(*(__half2*)&u.x);
        float2 f1 = __half22float2(*(__half2*)&u.y);
        acc.x += f0.x; acc.y += f0.y; acc.z += f1.x; acc.w += f1.y;
    }
    uint2 o;
    *(__half2*)&o.x = __floats2half2_rn(acc.x, acc.y);
    *(__half2*)&o.y = __floats2half2_rn(acc.z, acc.w);
    ((uint2*)agg)[(size_t)w * 32 + lane] = o;
}

// ---------------- indexed CSR aggregation (compacted over idxlist) ----------------
// warp j: gather in-edges of node idxlist[j]; optionally skip masked src (zero rows);
// write compacted agg[j].
__global__ void __launch_bounds__(256)
k_agg_idx(const __half* __restrict__ S,
          const int* __restrict__ rowptr, const int* __restrict__ csrc,
          const int* __restrict__ maskflag, const int* __restrict__ idxlist,
          __half* __restrict__ agg, int cnt, int skip_masked) {
    int j = (blockIdx.x * blockDim.x + threadIdx.x) >> 5;
    int lane = threadIdx.x & 31;
    if (j >= cnt) return;
    int node = idxlist[j];
    int beg = rowptr[node];
    int end = rowptr[node + 1];
    float4 acc = make_float4(0.f, 0.f, 0.f, 0.f);
    for (int e = beg; e < end; e++) {
        int s = csrc[e];
        if (skip_masked && maskflag[s]) continue;
        uint2 u = ((const uint2*)S)[(size_t)s * 32 + lane];
        float2 f0 = __half22float2(*(__half2*)&u.x);
        float2 f1 = __half22float2(*(__half2*)&u.y);
        acc.x += f0.x; acc.y += f0.y; acc.z += f1.x; acc.w += f1.y;
    }
    uint2 o;
    *(__half2*)&o.x = __floats2half2_rn(acc.x, acc.y);
    *(__half2*)&o.y = __floats2half2_rn(acc.z, acc.w);
    ((uint2*)agg)[(size_t)j * 32 + lane] = o;
}

// ---------------- mma helper macros ----------------
#define MMA_LOOP(cacc, aBase, sWu, bRow, bKoff)                                              \
    _Pragma("unroll")                                                                         \
    for (int kb = 0; kb < 8; kb++) {                                                          \
        uint32_t a0, a1, a2, a3;                                                              \
        asm volatile("ldmatrix.sync.aligned.m8n8.x4.shared.b16 {%0,%1,%2,%3}, [%4];"         \
                     : "=r"(a0), "=r"(a1), "=r"(a2), "=r"(a3)                                 \
                     : "r"((aBase) + kb * 32));                                               \
        _Pragma("unroll")                                                                     \
        for (int ng = 0; ng < 8; ng++) {                                                      \
            uint32_t b0, b1, b2, b3;                                                          \
            uint32_t baddr = (sWu) + (uint32_t)((ng * 16 + (bRow)) * (SROW * 2) + kb * 32 + (bKoff)); \
            asm volatile("ldmatrix.sync.aligned.m8n8.x4.shared.b16 {%0,%1,%2,%3}, [%4];"     \
                         : "=r"(b0), "=r"(b1), "=r"(b2), "=r"(b3)                             \
                         : "r"(baddr));                                                       \
            int t0 = ng * 2, t1 = ng * 2 + 1;                                                 \
            asm volatile("mma.sync.aligned.m16n8k16.row.col.f32.f16.f16.f32 "                \
                         "{%0,%1,%2,%3}, {%4,%5,%6,%7}, {%8,%9}, {%0,%1,%2,%3};"             \
                         : "+f"(cacc[t0][0]), "+f"(cacc[t0][1]), "+f"(cacc[t0][2]), "+f"(cacc[t0][3]) \
                         : "r"(a0), "r"(a1), "r"(a2), "r"(a3), "r"(b0), "r"(b1));             \
            asm volatile("mma.sync.aligned.m16n8k16.row.col.f32.f16.f16.f32 "                \
                         "{%0,%1,%2,%3}, {%4,%5,%6,%7}, {%8,%9}, {%0,%1,%2,%3};"             \
                         : "+f"(cacc[t1][0]), "+f"(cacc[t1][1]), "+f"(cacc[t1][2]), "+f"(cacc[t1][3]) \
                         : "r"(a0), "r"(a1), "r"(a2), "r"(a3), "r"(b2), "r"(b3));             \
        }                                                                                     \
    }

#define STAGE_W(Wp, sW)                                                                       \
    _Pragma("unroll")                                                                         \
    for (int it = 0; it < 32; it++) {                                                         \
        int idx = it * 256 + threadIdx.x;                                                     \
        int base2 = idx * 2;                                                                  \
        int cc = base2 >> 7, kk = base2 & 127;                                                \
        float w0 = (Wp)[base2], w1 = (Wp)[base2 + 1];                                         \
        *(__half2*)&(sW)[cc * SROW + kk] = __floats2half2_rn(w0, w1);                         \
    }

#define STAGE_A(inp, sA, nrows)                                                               \
    _Pragma("unroll")                                                                         \
    for (int it = 0; it < 8; it++) {                                                          \
        int idx = it * 256 + threadIdx.x;                                                     \
        int r = idx >> 4, c8 = idx & 15;                                                      \
        uint4 v = make_uint4(0u, 0u, 0u, 0u);                                                 \
        int gr = row0 + r;                                                                    \
        if (gr < (nrows)) v = ((const uint4*)(inp))[(size_t)gr * 16 + c8];                    \
        *(uint4*)&(sA)[r * SROW + c8 * 8] = v;                                                \
    }

// ---------------- conv1 GEMM: (acc+b)*rs_in -> LN -> PReLU -> fp16 *rs_out -> S ----------
__global__ void __launch_bounds__(256, 2)
k_gemm1(const __half* __restrict__ in, __half* __restrict__ outh,
        const float* __restrict__ W, const float* __restrict__ bias,
        const float* __restrict__ rs_in, const float* __restrict__ rs_out,
        const float* __restrict__ gamma, const float* __restrict__ beta,
        const float* __restrict__ alpha, int n) {
    extern __shared__ char smraw[];
    __half* sA = (__half*)smraw;
    __half* sW = sA + 128 * SROW;
    float* sBias  = (float*)(sW + 128 * SROW);
    float* sGamma = sBias + 128;
    float* sBeta  = sGamma + 128;

    const int tid  = threadIdx.x;
    const int row0 = blockIdx.x * 128;

    STAGE_A(in, sA, n);
    STAGE_W(W, sW);
    if (tid < 128) { sBias[tid] = bias[tid]; sGamma[tid] = gamma[tid]; sBeta[tid] = beta[tid]; }
    __syncthreads();

    const int warp = tid >> 5;
    const int lane = tid & 31;
    float c[16][4];
    #pragma unroll
    for (int i = 0; i < 16; i++) { c[i][0]=0.f; c[i][1]=0.f; c[i][2]=0.f; c[i][3]=0.f; }

    uint32_t sAu = (uint32_t)__cvta_generic_to_shared(sA);
    uint32_t sWu = (uint32_t)__cvta_generic_to_shared(sW);
    uint32_t aBase = sAu + (uint32_t)((warp * 16 + (lane & 15)) * (SROW * 2) + (lane >> 4) * 16);
    uint32_t bRow  = (uint32_t)((lane >> 4) * 8 + (lane & 7));
    uint32_t bKoff = (uint32_t)(((lane >> 3) & 1) * 16);

    MMA_LOOP(c, aBase, sWu, bRow, bKoff);

    int r0 = row0 + warp * 16 + (lane >> 2);
    int r1 = r0 + 8;
    int q  = lane & 3;

    float rsi0 = (r0 < n) ? rs_in[r0] : 1.f;
    float rsi1 = (r1 < n) ? rs_in[r1] : 1.f;
    float s0 = 0.f, ss0 = 0.f, s1 = 0.f, ss1 = 0.f;
    #pragma unroll
    for (int ct = 0; ct < 16; ct++) {
        int colb = ct * 8 + q * 2;
        float bb0 = sBias[colb], bb1 = sBias[colb + 1];
        c[ct][0] = (c[ct][0] + bb0) * rsi0;
        c[ct][1] = (c[ct][1] + bb1) * rsi0;
        c[ct][2] = (c[ct][2] + bb0) * rsi1;
        c[ct][3] = (c[ct][3] + bb1) * rsi1;
        s0  += c[ct][0] + c[ct][1];
        ss0 += c[ct][0] * c[ct][0] + c[ct][1] * c[ct][1];
        s1  += c[ct][2] + c[ct][3];
        ss1 += c[ct][2] * c[ct][2] + c[ct][3] * c[ct][3];
    }
    #pragma unroll
    for (int o = 1; o <= 2; o <<= 1) {
        s0  += __shfl_xor_sync(0xffffffffu, s0,  o);
        ss0 += __shfl_xor_sync(0xffffffffu, ss0, o);
        s1  += __shfl_xor_sync(0xffffffffu, s1,  o);
        ss1 += __shfl_xor_sync(0xffffffffu, ss1, o);
    }
    float mu0 = s0 * (1.f / 128.f);
    float mu1 = s1 * (1.f / 128.f);
    float inv0 = rsqrtf(ss0 * (1.f / 128.f) - mu0 * mu0 + 1e-5f);
    float inv1 = rsqrtf(ss1 * (1.f / 128.f) - mu1 * mu1 + 1e-5f);
    float aP = alpha[0];
    float rso0 = (r0 < n) ? rs_out[r0] : 1.f;
    float rso1 = (r1 < n) ? rs_out[r1] : 1.f;
    #pragma unroll
    for (int ct = 0; ct < 16; ct++) {
        int colb = ct * 8 + q * 2;
        float g0 = sGamma[colb], g1 = sGamma[colb + 1];
        float e0 = sBeta[colb],  e1 = sBeta[colb + 1];
        float y0 = (c[ct][0] - mu0) * inv0 * g0 + e0; y0 = (y0 >= 0.f) ? y0 : aP * y0;
        float y1 = (c[ct][1] - mu0) * inv0 * g1 + e1; y1 = (y1 >= 0.f) ? y1 : aP * y1;
        float y2 = (c[ct][2] - mu1) * inv1 * g0 + e0; y2 = (y2 >= 0.f) ? y2 : aP * y2;
        float y3 = (c[ct][3] - mu1) * inv1 * g1 + e1; y3 = (y3 >= 0.f) ? y3 : aP * y3;
        int ci = ct * 4 + q;
        if (r0 < n) ((__half2*)outh)[(size_t)r0 * 64 + ci] = __floats2half2_rn(y0 * rso0, y1 * rso0);
        if (r1 < n) ((__half2*)outh)[(size_t)r1 * 64 + ci] = __floats2half2_rn(y2 * rso1, y3 * rso1);
    }
}

// ---------------- fused conv2-GEMM (LN+PReLU) + enc->dec-GEMM (*rs_out), compacted ----------
// rows are compacted non-masked nodes: row j -> node nonmask[j]. Epilogue scatters to S[node].
// No re-mask branch needed (all rows non-masked; S[masked] is stale but never read).
__global__ void __launch_bounds__(256, 2)
k_gemm_fused(const __half* __restrict__ in, __half* __restrict__ outS,
             const float* __restrict__ W2, const float* __restrict__ bias2,
             const float* __restrict__ We2d,
             const float* __restrict__ rs_in, const float* __restrict__ rs_out,
             const float* __restrict__ gamma, const float* __restrict__ beta,
             const float* __restrict__ alpha,
             const int* __restrict__ nonmask, int nm) {
    extern __shared__ char smraw[];
    __half* sA = (__half*)smraw;
    __half* sW = sA + 128 * SROW;
    float* sBias  = (float*)(sW + 128 * SROW);
    float* sGamma = sBias + 128;
    float* sBeta  = sGamma + 128;

    const int tid  = threadIdx.x;
    const int row0 = blockIdx.x * 128;

    STAGE_A(in, sA, nm);
    STAGE_W(W2, sW);
    if (tid < 128) { sBias[tid] = bias2[tid]; sGamma[tid] = gamma[tid]; sBeta[tid] = beta[tid]; }
    __syncthreads();

    const int warp = tid >> 5;
    const int lane = tid & 31;
    float c[16][4];
    #pragma unroll
    for (int i = 0; i < 16; i++) { c[i][0]=0.f; c[i][1]=0.f; c[i][2]=0.f; c[i][3]=0.f; }

    uint32_t sAu = (uint32_t)__cvta_generic_to_shared(sA);
    uint32_t sWu = (uint32_t)__cvta_generic_to_shared(sW);
    uint32_t aBase = sAu + (uint32_t)((warp * 16 + (lane & 15)) * (SROW * 2) + (lane >> 4) * 16);
    uint32_t bRow  = (uint32_t)((lane >> 4) * 8 + (lane & 7));
    uint32_t bKoff = (uint32_t)(((lane >> 3) & 1) * 16);

    MMA_LOOP(c, aBase, sWu, bRow, bKoff);

    int lr0 = warp * 16 + (lane >> 2);
    int lr1 = lr0 + 8;
    int r0 = row0 + lr0;
    int r1 = row0 + lr1;
    int q  = lane & 3;

    int node0 = (r0 < nm) ? nonmask[r0] : 0;
    int node1 = (r1 < nm) ? nonmask[r1] : 0;
    float rsi0 = (r0 < nm) ? rs_in[node0] : 1.f;
    float rsi1 = (r1 < nm) ? rs_in[node1] : 1.f;
    float s0 = 0.f, ss0 = 0.f, s1 = 0.f, ss1 = 0.f;
    #pragma unroll
    for (int ct = 0; ct < 16; ct++) {
        int colb = ct * 8 + q * 2;
        float bb0 = sBias[colb], bb1 = sBias[colb + 1];
        c[ct][0] = (c[ct][0] + bb0) * rsi0;
        c[ct][1] = (c[ct][1] + bb1) * rsi0;
        c[ct][2] = (c[ct][2] + bb0) * rsi1;
        c[ct][3] = (c[ct][3] + bb1) * rsi1;
        s0  += c[ct][0] + c[ct][1];
        ss0 += c[ct][0] * c[ct][0] + c[ct][1] * c[ct][1];
        s1  += c[ct][2] + c[ct][3];
        ss1 += c[ct][2] * c[ct][2] + c[ct][3] * c[ct][3];
    }
    #pragma unroll
    for (int o = 1; o <= 2; o <<= 1) {
        s0  += __shfl_xor_sync(0xffffffffu, s0,  o);
        ss0 += __shfl_xor_sync(0xffffffffu, ss0, o);
        s1  += __shfl_xor_sync(0xffffffffu, s1,  o);
        ss1 += __shfl_xor_sync(0xffffffffu, ss1, o);
    }
    float mu0 = s0 * (1.f / 128.f);
    float mu1 = s1 * (1.f / 128.f);
    float inv0 = rsqrtf(ss0 * (1.f / 128.f) - mu0 * mu0 + 1e-5f);
    float inv1 = rsqrtf(ss1 * (1.f / 128.f) - mu1 * mu1 + 1e-5f);
    float aP = alpha[0];
    #pragma unroll
    for (int ct = 0; ct < 16; ct++) {
        int colb = ct * 8 + q * 2;
        float g0 = sGamma[colb], g1 = sGamma[colb + 1];
        float e0 = sBeta[colb],  e1 = sBeta[colb + 1];
        float y0 = (c[ct][0] - mu0) * inv0 * g0 + e0; y0 = (y0 >= 0.f) ? y0 : aP * y0;
        float y1 = (c[ct][1] - mu0) * inv0 * g1 + e1; y1 = (y1 >= 0.f) ? y1 : aP * y1;
        float y2 = (c[ct][2] - mu1) * inv1 * g0 + e0; y2 = (y2 >= 0.f) ? y2 : aP * y2;
        float y3 = (c[ct][3] - mu1) * inv1 * g1 + e1; y3 = (y3 >= 0.f) ? y3 : aP * y3;
        *(__half2*)&sA[lr0 * SROW + colb] = __floats2half2_rn(y0, y1);
        *(__half2*)&sA[lr1 * SROW + colb] = __floats2half2_rn(y2, y3);
    }

    __syncthreads();
    STAGE_W(We2d, sW);
    __syncthreads();

    #pragma unroll
    for (int i = 0; i < 16; i++) { c[i][0]=0.f; c[i][1]=0.f; c[i][2]=0.f; c[i][3]=0.f; }
    MMA_LOOP(c, aBase, sWu, bRow, bKoff);

    float rso0 = (r0 < nm) ? rs_out[node0] : 0.f;
    float rso1 = (r1 < nm) ? rs_out[node1] : 0.f;
    #pragma unroll
    for (int ct = 0; ct < 16; ct++) {
        int ci = ct * 4 + q;
        if (r0 < nm) ((__half2*)outS)[(size_t)node0 * 64 + ci] = __floats2half2_rn(c[ct][0] * rso0, c[ct][1] * rso0);
        if (r1 < nm) ((__half2*)outS)[(size_t)node1 * 64 + ci] = __floats2half2_rn(c[ct][2] * rso1, c[ct][3] * rso1);
    }
}

// ---------------- decoder GEMM + fused SCE loss (compacted over m masked rows) ----------
__global__ void __launch_bounds__(256, 2)
k_gemm_loss(const __half* __restrict__ in, const float* __restrict__ x,
            const int* __restrict__ mask_nodes,
            const float* __restrict__ W, const float* __restrict__ bias,
            const float* __restrict__ rs_in,
            int m, float* __restrict__ out) {
    extern __shared__ char smraw[];
    __half* sA = (__half*)smraw;
    __half* sW = sA + 128 * SROW;
    float* sBias = (float*)(sW + 128 * SROW);
    float* sWsum = sBias + 128;     // [8] warp partial sums

    const int tid  = threadIdx.x;
    const int row0 = blockIdx.x * 128;

    STAGE_A(in, sA, m);
    STAGE_W(W, sW);
    if (tid < 128) sBias[tid] = bias[tid];
    __syncthreads();

    const int warp = tid >> 5;
    const int lane = tid & 31;
    float c[16][4];
    #pragma unroll
    for (int i = 0; i < 16; i++) { c[i][0]=0.f; c[i][1]=0.f; c[i][2]=0.f; c[i][3]=0.f; }

    uint32_t sAu = (uint32_t)__cvta_generic_to_shared(sA);
    uint32_t sWu = (uint32_t)__cvta_generic_to_shared(sW);
    uint32_t aBase = sAu + (uint32_t)((warp * 16 + (lane & 15)) * (SROW * 2) + (lane >> 4) * 16);
    uint32_t bRow  = (uint32_t)((lane >> 4) * 8 + (lane & 7));
    uint32_t bKoff = (uint32_t)(((lane >> 3) & 1) * 16);

    MMA_LOOP(c, aBase, sWu, bRow, bKoff);

    int r0 = row0 + warp * 16 + (lane >> 2);   // compacted row index
    int r1 = r0 + 8;
    int q  = lane & 3;

    int node0 = (r0 < m) ? mask_nodes[r0] : 0;
    int node1 = (r1 < m) ? mask_nodes[r1] : 0;
    float rsi0 = (r0 < m) ? rs_in[node0] : 0.f;
    float rsi1 = (r1 < m) ? rs_in[node1] : 0.f;

    float dot0 = 0.f, nr0 = 0.f, nx0 = 0.f;
    float dot1 = 0.f, nr1 = 0.f, nx1 = 0.f;
    const float* xp0 = x + (size_t)node0 * DD;
    const float* xp1 = x + (size_t)node1 * DD;
    #pragma unroll
    for (int ct = 0; ct < 16; ct++) {
        int colb = ct * 8 + q * 2;
        float bb0 = sBias[colb], bb1 = sBias[colb + 1];
        float v0 = (c[ct][0] + bb0) * rsi0;
        float v1 = (c[ct][1] + bb1) * rsi0;
        float v2 = (c[ct][2] + bb0) * rsi1;
        float v3 = (c[ct][3] + bb1) * rsi1;
        float xa0 = (r0 < m) ? xp0[colb]     : 0.f;
        float xa1 = (r0 < m) ? xp0[colb + 1] : 0.f;
        float xb0 = (r1 < m) ? xp1[colb]     : 0.f;
        float xb1 = (r1 < m) ? xp1[colb + 1] : 0.f;
        dot0 += v0 * xa0 + v1 * xa1;
        nr0  += v0 * v0 + v1 * v1;
        nx0  += xa0 * xa0 + xa1 * xa1;
        dot1 += v2 * xb0 + v3 * xb1;
        nr1  += v2 * v2 + v3 * v3;
        nx1  += xb0 * xb0 + xb1 * xb1;
    }
    #pragma unroll
    for (int o = 1; o <= 2; o <<= 1) {
        dot0 += __shfl_xor_sync(0xffffffffu, dot0, o);
        nr0  += __shfl_xor_sync(0xffffffffu, nr0,  o);
        nx0  += __shfl_xor_sync(0xffffffffu, nx0,  o);
        dot1 += __shfl_xor_sync(0xffffffffu, dot1, o);
        nr1  += __shfl_xor_sync(0xffffffffu, nr1,  o);
        nx1  += __shfl_xor_sync(0xffffffffu, nx1,  o);
    }
    float term = 0.f;
    if (q == 0) {
        if (r0 < m) {
            float cc = dot0 / (fmaxf(sqrtf(nr0), 1e-12f) * fmaxf(sqrtf(nx0), 1e-12f));
            float t = 1.f - cc;
            term += t * t;
        }
        if (r1 < m) {
            float cc = dot1 / (fmaxf(sqrtf(nr1), 1e-12f) * fmaxf(sqrtf(nx1), 1e-12f));
            float t = 1.f - cc;
            term += t * t;
        }
    }
    #pragma unroll
    for (int o = 4; o <= 16; o <<= 1) term += __shfl_xor_sync(0xffffffffu, term, o);
    if (lane == 0) sWsum[warp] = term;
    __syncthreads();
    if (tid == 0) {
        float s = 0.f;
        #pragma unroll
        for (int i = 0; i < 8; i++) s += sWsum[i];
        atomicAdd(out, s / (float)m);
    }
}

// ---------------- launch ----------------
extern "C" void kernel_launch(void* const* d_in, const int* in_sizes, int n_in,
                              void* d_out, int out_size) {
    const float* x     = (const float*)d_in[0];
    const float* token = (const float*)d_in[1];
    const float* W1    = (const float*)d_in[2];
    const float* b1    = (const float*)d_in[3];
    const float* g1    = (const float*)d_in[4];
    const float* be1   = (const float*)d_in[5];
    const float* a1    = (const float*)d_in[6];
    const float* W2    = (const float*)d_in[7];
    const float* b2    = (const float*)d_in[8];
    const float* g2    = (const float*)d_in[9];
    const float* be2   = (const float*)d_in[10];
    const float* a2    = (const float*)d_in[11];
    const float* We2d  = (const float*)d_in[12];
    const float* Wd    = (const float*)d_in[13];
    const float* bd    = (const float*)d_in[14];
    const int*   src   = (const int*)d_in[15];
    const int*   dst   = (const int*)d_in[16];
    const int*   mask  = (const int*)d_in[17];

    const int n = in_sizes[0] / DD;
    const int E = in_sizes[15];
    const int M = in_sizes[17];
    const int NM = n - M;               // non-masked node count (mask indices are unique)
    float* out = (float*)d_out;

    float *tokA, *rs_out, *rs_in;
    __half *S, *agg16;
    int *deg_out, *deg_in, *maskflag, *rowptr, *fill, *csrc, *bsum, *nonmask, *nmcount;
    cudaGetSymbolAddress((void**)&S,     g_S);
    cudaGetSymbolAddress((void**)&agg16, g_agg16);
    cudaGetSymbolAddress((void**)&tokA,  g_token);
    cudaGetSymbolAddress((void**)&deg_out, g_deg_out);
    cudaGetSymbolAddress((void**)&deg_in,  g_deg_in);
    cudaGetSymbolAddress((void**)&rs_out, g_rs_out);
    cudaGetSymbolAddress((void**)&rs_in,  g_rs_in);
    cudaGetSymbolAddress((void**)&maskflag, g_maskflag);
    cudaGetSymbolAddress((void**)&rowptr, g_rowptr);
    cudaGetSymbolAddress((void**)&fill,   g_fill);
    cudaGetSymbolAddress((void**)&csrc,   g_csrc);
    cudaGetSymbolAddress((void**)&bsum,   g_bsum);
    cudaGetSymbolAddress((void**)&nonmask, g_nonmask);
    cudaGetSymbolAddress((void**)&nmcount, g_nmcount);

    const size_t smem = (size_t)(2 * 128 * SROW) * sizeof(__half) + 3 * 128 * sizeof(float);
    cudaFuncSetAttribute(k_gemm1, cudaFuncAttributeMaxDynamicSharedMemorySize, (int)smem);
    cudaFuncSetAttribute(k_gemm_fused, cudaFuncAttributeMaxDynamicSharedMemorySize, (int)smem);
    cudaFuncSetAttribute(k_gemm_loss, cudaFuncAttributeMaxDynamicSharedMemorySize, (int)smem);

    const int T = 256;
    const int gN  = (n + T - 1) / T;
    const int gE  = (E + T - 1) / T;
    const int gW  = ((n * 32) + T - 1) / T;
    const int gWM = ((M * 32) + T - 1) / T;
    const int gWN = ((NM * 32) + T - 1) / T;
    const int gG  = (n + 127) / 128;
    const int gGN = (NM + 127) / 128;
    const int gGM = (M + 127) / 128;
    const int nb  = (n + 1 + 1023) / 1024;

    // setup
    k_init <<<gN, T>>>(token, tokA, deg_out, deg_in, fill, maskflag, nmcount, out, n);
    k_deg  <<<gE, T>>>(src, dst, deg_out, deg_in, E);
    k_post <<<gN, T>>>(mask, maskflag, M, deg_out, deg_in, rs_out, rs_in, n);
    k_scan1<<<nb, 1024>>>(deg_in, rowptr, bsum, n);
    k_scan3<<<nb, 1024>>>(rowptr, bsum, maskflag, nonmask, nmcount, n);
    k_fill <<<gE, T>>>(src, dst, rowptr, fill, csrc, E);

    // conv1 (all nodes)
    k_prep1<<<gW, T>>>(x, tokA, maskflag, rs_out, S, n);
    k_agg  <<<gW, T>>>(S, rowptr, csrc, agg16, n);
    k_gemm1<<<gG, 256, smem>>>(agg16, S, W1, b1, rs_in, rs_out, g1, be1, a1, n);

    // conv2 + enc->dec (compacted over non-masked nodes)
    k_agg_idx<<<gWN, T>>>(S, rowptr, csrc, maskflag, nonmask, agg16, NM, 0);
    k_gemm_fused<<<gGN, 256, smem>>>(agg16, S, W2, b2, We2d, rs_in, rs_out, g2, be2, a2, nonmask, NM);

    // decoder conv + loss (compacted over masked nodes, skip masked src)
    k_agg_idx<<<gWM, T>>>(S, rowptr, csrc, maskflag, mask, agg16, M, 1);
    k_gemm_loss<<<gGM, 256, smem>>>(agg16, x, mask, Wd, bd, rs_in, M, out);
}

// round 14
// speedup vs baseline: 1.4888x; 1.0367x over previous
#include <cuda_runtime.h>
#include <cuda_fp16.h>
#include <cstdint>
#include <stdint.h>
#include <math.h>

#define DD 128
#define NMAX 50000
#define EMAX 800000
#define SROW 136            // smem row stride in halfs (272B, 16B-multiple)

// ---------------- scratch (static device globals; zero-initialized at load,
// re-zeroed by the tail of every launch for the next replay) ----------------
__device__ __align__(16) __half g_S[(size_t)NMAX * DD];       // rs_out-scaled gather rows
__device__ __align__(16) __half g_agg16[(size_t)NMAX * DD];   // aggregation output (fp16)
__device__ __align__(16) float  g_token[DD];
__device__ int   g_deg_out[NMAX];     // must be 0 at launch start
__device__ int   g_deg_in[NMAX];      // must be 0 at launch start
__device__ float g_rs_out[NMAX];
__device__ float g_rs_in[NMAX];
__device__ int   g_maskflag[NMAX];    // must be 0 at launch start
__device__ int   g_rowptr[NMAX + 1];
__device__ int   g_bsum[128];
__device__ int   g_nonmask[NMAX];
__device__ int   g_nmcount;           // must be 0 at launch start
__device__ int   g_eslot[EMAX];
__device__ int   g_csrc[EMAX];

// ---------------- k_deg: degree count; atomic return value = CSR fill slot ----------------
__global__ void k_deg(const int* __restrict__ src, const int* __restrict__ dst,
                      int* __restrict__ dout, int* __restrict__ din,
                      int* __restrict__ eslot, int e) {
    int i = blockIdx.x * blockDim.x + threadIdx.x;
    if (i < e) {
        atomicAdd(&dout[src[i]], 1);
        eslot[i] = atomicAdd(&din[dst[i]], 1);
    }
}

// ---------------- k_scan1: per-tile exclusive scan + rsqrt norms + mask mark + token + out ----
__global__ void __launch_bounds__(1024)
k_scan1(const int* __restrict__ din, const int* __restrict__ dout,
        int* __restrict__ rowptr, int* __restrict__ bsum,
        const int* __restrict__ mask_nodes, int* __restrict__ maskflag, int m,
        float* __restrict__ ro, float* __restrict__ ri,
        const float* __restrict__ token, float* __restrict__ tok,
        float* __restrict__ out, int n) {
    __shared__ int warpsum[32];
    int t = threadIdx.x;
    int gi = blockIdx.x * 1024 + t;
    int lane = t & 31, wid = t >> 5;

    int v = (gi < n) ? din[gi] : 0;

    // fused elementwise work (independent of scan)
    if (gi < n) {
        ro[gi] = rsqrtf(fmaxf((float)dout[gi], 1.f));
        ri[gi] = rsqrtf(fmaxf((float)v, 1.f));
    }
    if (gi < m) maskflag[mask_nodes[gi]] = 1;
    if (gi < DD) tok[gi] = token[gi];
    if (gi == 0) out[0] = 0.f;

    // tile-local exclusive scan of din
    int inc = v;
    #pragma unroll
    for (int o = 1; o < 32; o <<= 1) {
        int u = __shfl_up_sync(0xffffffffu, inc, o);
        if (lane >= o) inc += u;
    }
    if (lane == 31) warpsum[wid] = inc;
    __syncthreads();
    if (wid == 0) {
        int w = warpsum[lane];
        #pragma unroll
        for (int o = 1; o < 32; o <<= 1) {
            int u = __shfl_up_sync(0xffffffffu, w, o);
            if (lane >= o) w += u;
        }
        warpsum[lane] = w;
    }
    __syncthreads();
    int woff = (wid > 0) ? warpsum[wid - 1] : 0;
    if (gi <= n) rowptr[gi] = woff + inc - v;
    if (t == 1023) bsum[blockIdx.x] = warpsum[31];
}

// ---------------- k_scan3: add block offsets + build nonmask list ----------------
__global__ void __launch_bounds__(1024)
k_scan3(int* __restrict__ rowptr, const int* __restrict__ bsum,
        const int* __restrict__ maskflag, int* __restrict__ nonmask,
        int* __restrict__ nmcount, int n) {
    __shared__ int soff;
    int t = threadIdx.x;
    if (t < 32) {
        int ssum = 0;
        for (int i = t; i < blockIdx.x; i += 32) ssum += bsum[i];
        #pragma unroll
        for (int o = 16; o; o >>= 1) ssum += __shfl_xor_sync(0xffffffffu, ssum, o);
        if (t == 0) soff = ssum;
    }
    __syncthreads();
    int gi = blockIdx.x * 1024 + t;
    if (gi <= n) rowptr[gi] += soff;
    if (gi < n && !maskflag[gi]) {
        int p = atomicAdd(nmcount, 1);
        nonmask[p] = gi;
    }
}

// ---------------- k_fill: atomic-free CSR fill using precomputed slots ----------------
__global__ void k_fill(const int* __restrict__ src, const int* __restrict__ dst,
                       const int* __restrict__ rowptr, const int* __restrict__ eslot,
                       int* __restrict__ csrc, int e) {
    int i = blockIdx.x * blockDim.x + threadIdx.x;
    if (i < e) {
        int d = dst[i];
        csrc[rowptr[d] + eslot[i]] = src[i];
    }
}

// ---------------- prep: S[v] = (mask? token : x[v]) * rs_out[v] fp16 ----------------
__global__ void __launch_bounds__(256)
k_prep1(const float* __restrict__ x, const float* __restrict__ token,
        const int* __restrict__ maskflag, const float* __restrict__ rs_out,
        __half* __restrict__ S, int n) {
    int w = (blockIdx.x * blockDim.x + threadIdx.x) >> 5;
    int lane = threadIdx.x & 31;
    if (w >= n) return;
    float r = rs_out[w];
    const float* srcp = maskflag[w] ? (token + lane * 4) : (x + (size_t)w * DD + lane * 4);
    __half2 p0 = __floats2half2_rn(srcp[0] * r, srcp[1] * r);
    __half2 p1 = __floats2half2_rn(srcp[2] * r, srcp[3] * r);
    uint2 u;
    *(__half2*)&u.x = p0;
    *(__half2*)&u.y = p1;
    ((uint2*)S)[(size_t)w * 32 + lane] = u;
}

// ---------------- CSR aggregation over all nodes ----------------
__global__ void __launch_bounds__(256)
k_agg(const __half* __restrict__ S,
      const int* __restrict__ rowptr, const int* __restrict__ csrc,
      __half* __restrict__ agg, int n) {
    int w = (blockIdx.x * blockDim.x + threadIdx.x) >> 5;
    int lane = threadIdx.x & 31;
    if (w >= n) return;
    int beg = rowptr[w];
    int end = rowptr[w + 1];
    float4 acc = make_float4(0.f, 0.f, 0.f, 0.f);
    for (int e = beg; e < end; e++) {
        int s = csrc[e];
        uint2 u = ((const uint2*)S)[(size_t)s * 32 + lane];
        float2 f0 = __half22float2(*(__half2*)&u.x);
        float2 f1 = __half22float2(*(__half2*)&u.y);
        acc.x += f0.x; acc.y += f0.y; acc.z += f1.x; acc.w += f1.y;
    }
    uint2 o;
    *(__half2*)&o.x = __floats2half2_rn(acc.x, acc.y);
    *(__half2*)&o.y = __floats2half2_rn(acc.z, acc.w);
    ((uint2*)agg)[(size_t)w * 32 + lane] = o;
}

// ---------------- indexed CSR aggregation (compacted over idxlist) ----------------
__global__ void __launch_bounds__(256)
k_agg_idx(const __half* __restrict__ S,
          const int* __restrict__ rowptr, const int* __restrict__ csrc,
          const int* __restrict__ maskflag, const int* __restrict__ idxlist,
          __half* __restrict__ agg, int cnt, int skip_masked) {
    int j = (blockIdx.x * blockDim.x + threadIdx.x) >> 5;
    int lane = threadIdx.x & 31;
    if (j >= cnt) return;
    int node = idxlist[j];
    int beg = rowptr[node];
    int end = rowptr[node + 1];
    float4 acc = make_float4(0.f, 0.f, 0.f, 0.f);
    for (int e = beg; e < end; e++) {
        int s = csrc[e];
        if (skip_masked && maskflag[s]) continue;
        uint2 u = ((const uint2*)S)[(size_t)s * 32 + lane];
        float2 f0 = __half22float2(*(__half2*)&u.x);
        float2 f1 = __half22float2(*(__half2*)&u.y);
        acc.x += f0.x; acc.y += f0.y; acc.z += f1.x; acc.w += f1.y;
    }
    uint2 o;
    *(__half2*)&o.x = __floats2half2_rn(acc.x, acc.y);
    *(__half2*)&o.y = __floats2half2_rn(acc.z, acc.w);
    ((uint2*)agg)[(size_t)j * 32 + lane] = o;
}

// ---------------- mma helper macros ----------------
#define MMA_LOOP(cacc, aBase, sWu, bRow, bKoff)                                              \
    _Pragma("unroll")                                                                         \
    for (int kb = 0; kb < 8; kb++) {                                                          \
        uint32_t a0, a1, a2, a3;                                                              \
        asm volatile("ldmatrix.sync.aligned.m8n8.x4.shared.b16 {%0,%1,%2,%3}, [%4];"         \
                     : "=r"(a0), "=r"(a1), "=r"(a2), "=r"(a3)                                 \
                     : "r"((aBase) + kb * 32));                                               \
        _Pragma("unroll")                                                                     \
        for (int ng = 0; ng < 8; ng++) {                                                      \
            uint32_t b0, b1, b2, b3;                                                          \
            uint32_t baddr = (sWu) + (uint32_t)((ng * 16 + (bRow)) * (SROW * 2) + kb * 32 + (bKoff)); \
            asm volatile("ldmatrix.sync.aligned.m8n8.x4.shared.b16 {%0,%1,%2,%3}, [%4];"     \
                         : "=r"(b0), "=r"(b1), "=r"(b2), "=r"(b3)                             \
                         : "r"(baddr));                                                       \
            int t0 = ng * 2, t1 = ng * 2 + 1;                                                 \
            asm volatile("mma.sync.aligned.m16n8k16.row.col.f32.f16.f16.f32 "                \
                         "{%0,%1,%2,%3}, {%4,%5,%6,%7}, {%8,%9}, {%0,%1,%2,%3};"             \
                         : "+f"(cacc[t0][0]), "+f"(cacc[t0][1]), "+f"(cacc[t0][2]), "+f"(cacc[t0][3]) \
                         : "r"(a0), "r"(a1), "r"(a2), "r"(a3), "r"(b0), "r"(b1));             \
            asm volatile("mma.sync.aligned.m16n8k16.row.col.f32.f16.f16.f32 "                \
                         "{%0,%1,%2,%3}, {%4,%5,%6,%7}, {%8,%9}, {%0,%1,%2,%3};"             \
                         : "+f"(cacc[t1][0]), "+f"(cacc[t1][1]), "+f"(cacc[t1][2]), "+f"(cacc[t1][3]) \
                         : "r"(a0), "r"(a1), "r"(a2), "r"(a3), "r"(b2), "r"(b3));             \
        }                                                                                     \
    }

#define STAGE_W(Wp, sW)                                                                       \
    _Pragma("unroll")                                                                         \
    for (int it = 0; it < 32; it++) {                                                         \
        int idx = it * 256 + threadIdx.x;                                                     \
        int base2 = idx * 2;                                                                  \
        int cc = base2 >> 7, kk = base2 & 127;                                                \
        float w0 = (Wp)[base2], w1 = (Wp)[base2 + 1];                                         \
        *(__half2*)&(sW)[cc * SROW + kk] = __floats2half2_rn(w0, w1);                         \
    }

#define STAGE_A(inp, sA, nrows)                                                               \
    _Pragma("unroll")                                                                         \
    for (int it = 0; it < 8; it++) {                                                          \
        int idx = it * 256 + threadIdx.x;                                                     \
        int r = idx >> 4, c8 = idx & 15;                                                      \
        uint4 v = make_uint4(0u, 0u, 0u, 0u);                                                 \
        int gr = row0 + r;                                                                    \
        if (gr < (nrows)) v = ((const uint4*)(inp))[(size_t)gr * 16 + c8];                    \
        *(uint4*)&(sA)[r * SROW + c8 * 8] = v;                                                \
    }

// ---------------- conv1 GEMM: (acc+b)*rs_in -> LN -> PReLU -> fp16 *rs_out -> S ----------
__global__ void __launch_bounds__(256, 2)
k_gemm1(const __half* __restrict__ in, __half* __restrict__ outh,
        const float* __restrict__ W, const float* __restrict__ bias,
        const float* __restrict__ rs_in, const float* __restrict__ rs_out,
        const float* __restrict__ gamma, const float* __restrict__ beta,
        const float* __restrict__ alpha, int n) {
    extern __shared__ char smraw[];
    __half* sA = (__half*)smraw;
    __half* sW = sA + 128 * SROW;
    float* sBias  = (float*)(sW + 128 * SROW);
    float* sGamma = sBias + 128;
    float* sBeta  = sGamma + 128;

    const int tid  = threadIdx.x;
    const int row0 = blockIdx.x * 128;

    STAGE_A(in, sA, n);
    STAGE_W(W, sW);
    if (tid < 128) { sBias[tid] = bias[tid]; sGamma[tid] = gamma[tid]; sBeta[tid] = beta[tid]; }
    __syncthreads();

    const int warp = tid >> 5;
    const int lane = tid & 31;
    float c[16][4];
    #pragma unroll
    for (int i = 0; i < 16; i++) { c[i][0]=0.f; c[i][1]=0.f; c[i][2]=0.f; c[i][3]=0.f; }

    uint32_t sAu = (uint32_t)__cvta_generic_to_shared(sA);
    uint32_t sWu = (uint32_t)__cvta_generic_to_shared(sW);
    uint32_t aBase = sAu + (uint32_t)((warp * 16 + (lane & 15)) * (SROW * 2) + (lane >> 4) * 16);
    uint32_t bRow  = (uint32_t)((lane >> 4) * 8 + (lane & 7));
    uint32_t bKoff = (uint32_t)(((lane >> 3) & 1) * 16);

    MMA_LOOP(c, aBase, sWu, bRow, bKoff);

    int r0 = row0 + warp * 16 + (lane >> 2);
    int r1 = r0 + 8;
    int q  = lane & 3;

    float rsi0 = (r0 < n) ? rs_in[r0] : 1.f;
    float rsi1 = (r1 < n) ? rs_in[r1] : 1.f;
    float s0 = 0.f, ss0 = 0.f, s1 = 0.f, ss1 = 0.f;
    #pragma unroll
    for (int ct = 0; ct < 16; ct++) {
        int colb = ct * 8 + q * 2;
        float bb0 = sBias[colb], bb1 = sBias[colb + 1];
        c[ct][0] = (c[ct][0] + bb0) * rsi0;
        c[ct][1] = (c[ct][1] + bb1) * rsi0;
        c[ct][2] = (c[ct][2] + bb0) * rsi1;
        c[ct][3] = (c[ct][3] + bb1) * rsi1;
        s0  += c[ct][0] + c[ct][1];
        ss0 += c[ct][0] * c[ct][0] + c[ct][1] * c[ct][1];
        s1  += c[ct][2] + c[ct][3];
        ss1 += c[ct][2] * c[ct][2] + c[ct][3] * c[ct][3];
    }
    #pragma unroll
    for (int o = 1; o <= 2; o <<= 1) {
        s0  += __shfl_xor_sync(0xffffffffu, s0,  o);
        ss0 += __shfl_xor_sync(0xffffffffu, ss0, o);
        s1  += __shfl_xor_sync(0xffffffffu, s1,  o);
        ss1 += __shfl_xor_sync(0xffffffffu, ss1, o);
    }
    float mu0 = s0 * (1.f / 128.f);
    float mu1 = s1 * (1.f / 128.f);
    float inv0 = rsqrtf(ss0 * (1.f / 128.f) - mu0 * mu0 + 1e-5f);
    float inv1 = rsqrtf(ss1 * (1.f / 128.f) - mu1 * mu1 + 1e-5f);
    float aP = alpha[0];
    float rso0 = (r0 < n) ? rs_out[r0] : 1.f;
    float rso1 = (r1 < n) ? rs_out[r1] : 1.f;
    #pragma unroll
    for (int ct = 0; ct < 16; ct++) {
        int colb = ct * 8 + q * 2;
        float g0 = sGamma[colb], g1 = sGamma[colb + 1];
        float e0 = sBeta[colb],  e1 = sBeta[colb + 1];
        float y0 = (c[ct][0] - mu0) * inv0 * g0 + e0; y0 = (y0 >= 0.f) ? y0 : aP * y0;
        float y1 = (c[ct][1] - mu0) * inv0 * g1 + e1; y1 = (y1 >= 0.f) ? y1 : aP * y1;
        float y2 = (c[ct][2] - mu1) * inv1 * g0 + e0; y2 = (y2 >= 0.f) ? y2 : aP * y2;
        float y3 = (c[ct][3] - mu1) * inv1 * g1 + e1; y3 = (y3 >= 0.f) ? y3 : aP * y3;
        int ci = ct * 4 + q;
        if (r0 < n) ((__half2*)outh)[(size_t)r0 * 64 + ci] = __floats2half2_rn(y0 * rso0, y1 * rso0);
        if (r1 < n) ((__half2*)outh)[(size_t)r1 * 64 + ci] = __floats2half2_rn(y2 * rso1, y3 * rso1);
    }
}

// ---------------- fused conv2-GEMM (LN+PReLU) + enc->dec-GEMM (*rs_out), compacted ----------
__global__ void __launch_bounds__(256, 2)
k_gemm_fused(const __half* __restrict__ in, __half* __restrict__ outS,
             const float* __restrict__ W2, const float* __restrict__ bias2,
             const float* __restrict__ We2d,
             const float* __restrict__ rs_in, const float* __restrict__ rs_out,
             const float* __restrict__ gamma, const float* __restrict__ beta,
             const float* __restrict__ alpha,
             const int* __restrict__ nonmask, int nm) {
    extern __shared__ char smraw[];
    __half* sA = (__half*)smraw;
    __half* sW = sA + 128 * SROW;
    float* sBias  = (float*)(sW + 128 * SROW);
    float* sGamma = sBias + 128;
    float* sBeta  = sGamma + 128;

    const int tid  = threadIdx.x;
    const int row0 = blockIdx.x * 128;

    STAGE_A(in, sA, nm);
    STAGE_W(W2, sW);
    if (tid < 128) { sBias[tid] = bias2[tid]; sGamma[tid] = gamma[tid]; sBeta[tid] = beta[tid]; }
    __syncthreads();

    const int warp = tid >> 5;
    const int lane = tid & 31;
    float c[16][4];
    #pragma unroll
    for (int i = 0; i < 16; i++) { c[i][0]=0.f; c[i][1]=0.f; c[i][2]=0.f; c[i][3]=0.f; }

    uint32_t sAu = (uint32_t)__cvta_generic_to_shared(sA);
    uint32_t sWu = (uint32_t)__cvta_generic_to_shared(sW);
    uint32_t aBase = sAu + (uint32_t)((warp * 16 + (lane & 15)) * (SROW * 2) + (lane >> 4) * 16);
    uint32_t bRow  = (uint32_t)((lane >> 4) * 8 + (lane & 7));
    uint32_t bKoff = (uint32_t)(((lane >> 3) & 1) * 16);

    MMA_LOOP(c, aBase, sWu, bRow, bKoff);

    int lr0 = warp * 16 + (lane >> 2);
    int lr1 = lr0 + 8;
    int r0 = row0 + lr0;
    int r1 = row0 + lr1;
    int q  = lane & 3;

    int node0 = (r0 < nm) ? nonmask[r0] : 0;
    int node1 = (r1 < nm) ? nonmask[r1] : 0;
    float rsi0 = (r0 < nm) ? rs_in[node0] : 1.f;
    float rsi1 = (r1 < nm) ? rs_in[node1] : 1.f;
    float s0 = 0.f, ss0 = 0.f, s1 = 0.f, ss1 = 0.f;
    #pragma unroll
    for (int ct = 0; ct < 16; ct++) {
        int colb = ct * 8 + q * 2;
        float bb0 = sBias[colb], bb1 = sBias[colb + 1];
        c[ct][0] = (c[ct][0] + bb0) * rsi0;
        c[ct][1] = (c[ct][1] + bb1) * rsi0;
        c[ct][2] = (c[ct][2] + bb0) * rsi1;
        c[ct][3] = (c[ct][3] + bb1) * rsi1;
        s0  += c[ct][0] + c[ct][1];
        ss0 += c[ct][0] * c[ct][0] + c[ct][1] * c[ct][1];
        s1  += c[ct][2] + c[ct][3];
        ss1 += c[ct][2] * c[ct][2] + c[ct][3] * c[ct][3];
    }
    #pragma unroll
    for (int o = 1; o <= 2; o <<= 1) {
        s0  += __shfl_xor_sync(0xffffffffu, s0,  o);
        ss0 += __shfl_xor_sync(0xffffffffu, ss0, o);
        s1  += __shfl_xor_sync(0xffffffffu, s1,  o);
        ss1 += __shfl_xor_sync(0xffffffffu, ss1, o);
    }
    float mu0 = s0 * (1.f / 128.f);
    float mu1 = s1 * (1.f / 128.f);
    float inv0 = rsqrtf(ss0 * (1.f / 128.f) - mu0 * mu0 + 1e-5f);
    float inv1 = rsqrtf(ss1 * (1.f / 128.f) - mu1 * mu1 + 1e-5f);
    float aP = alpha[0];
    #pragma unroll
    for (int ct = 0; ct < 16; ct++) {
        int colb = ct * 8 + q * 2;
        float g0 = sGamma[colb], g1 = sGamma[colb + 1];
        float e0 = sBeta[colb],  e1 = sBeta[colb + 1];
        float y0 = (c[ct][0] - mu0) * inv0 * g0 + e0; y0 = (y0 >= 0.f) ? y0 : aP * y0;
        float y1 = (c[ct][1] - mu0) * inv0 * g1 + e1; y1 = (y1 >= 0.f) ? y1 : aP * y1;
        float y2 = (c[ct][2] - mu1) * inv1 * g0 + e0; y2 = (y2 >= 0.f) ? y2 : aP * y2;
        float y3 = (c[ct][3] - mu1) * inv1 * g1 + e1; y3 = (y3 >= 0.f) ? y3 : aP * y3;
        *(__half2*)&sA[lr0 * SROW + colb] = __floats2half2_rn(y0, y1);
        *(__half2*)&sA[lr1 * SROW + colb] = __floats2half2_rn(y2, y3);
    }

    __syncthreads();
    STAGE_W(We2d, sW);
    __syncthreads();

    #pragma unroll
    for (int i = 0; i < 16; i++) { c[i][0]=0.f; c[i][1]=0.f; c[i][2]=0.f; c[i][3]=0.f; }
    MMA_LOOP(c, aBase, sWu, bRow, bKoff);

    float rso0 = (r0 < nm) ? rs_out[node0] : 0.f;
    float rso1 = (r1 < nm) ? rs_out[node1] : 0.f;
    #pragma unroll
    for (int ct = 0; ct < 16; ct++) {
        int ci = ct * 4 + q;
        if (r0 < nm) ((__half2*)outS)[(size_t)node0 * 64 + ci] = __floats2half2_rn(c[ct][0] * rso0, c[ct][1] * rso0);
        if (r1 < nm) ((__half2*)outS)[(size_t)node1 * 64 + ci] = __floats2half2_rn(c[ct][2] * rso1, c[ct][3] * rso1);
    }
}

// ---------------- decoder GEMM + fused SCE loss + tail cleanup for next replay ----------
__global__ void __launch_bounds__(256, 2)
k_gemm_loss(const __half* __restrict__ in, const float* __restrict__ x,
            const int* __restrict__ mask_nodes,
            const float* __restrict__ W, const float* __restrict__ bias,
            const float* __restrict__ rs_in,
            int m, float* __restrict__ out,
            int* __restrict__ deg_out, int* __restrict__ deg_in,
            int* __restrict__ maskflag, int* __restrict__ nmcount, int n) {
    extern __shared__ char smraw[];
    __half* sA = (__half*)smraw;
    __half* sW = sA + 128 * SROW;
    float* sBias = (float*)(sW + 128 * SROW);
    float* sWsum = sBias + 128;     // [8] warp partial sums

    const int tid  = threadIdx.x;
    const int row0 = blockIdx.x * 128;

    // tail cleanup: restore zero-state invariants for the next graph replay
    // (these arrays are not read by this kernel)
    for (int i = blockIdx.x * blockDim.x + tid; i < n; i += gridDim.x * blockDim.x) {
        deg_out[i] = 0; deg_in[i] = 0; maskflag[i] = 0;
    }
    if (blockIdx.x == 0 && tid == 0) *nmcount = 0;

    STAGE_A(in, sA, m);
    STAGE_W(W, sW);
    if (tid < 128) sBias[tid] = bias[tid];
    __syncthreads();

    const int warp = tid >> 5;
    const int lane = tid & 31;
    float c[16][4];
    #pragma unroll
    for (int i = 0; i < 16; i++) { c[i][0]=0.f; c[i][1]=0.f; c[i][2]=0.f; c[i][3]=0.f; }

    uint32_t sAu = (uint32_t)__cvta_generic_to_shared(sA);
    uint32_t sWu = (uint32_t)__cvta_generic_to_shared(sW);
    uint32_t aBase = sAu + (uint32_t)((warp * 16 + (lane & 15)) * (SROW * 2) + (lane >> 4) * 16);
    uint32_t bRow  = (uint32_t)((lane >> 4) * 8 + (lane & 7));
    uint32_t bKoff = (uint32_t)(((lane >> 3) & 1) * 16);

    MMA_LOOP(c, aBase, sWu, bRow, bKoff);

    int r0 = row0 + warp * 16 + (lane >> 2);   // compacted row index
    int r1 = r0 + 8;
    int q  = lane & 3;

    int node0 = (r0 < m) ? mask_nodes[r0] : 0;
    int node1 = (r1 < m) ? mask_nodes[r1] : 0;
    float rsi0 = (r0 < m) ? rs_in[node0] : 0.f;
    float rsi1 = (r1 < m) ? rs_in[node1] : 0.f;

    float dot0 = 0.f, nr0 = 0.f, nx0 = 0.f;
    float dot1 = 0.f, nr1 = 0.f, nx1 = 0.f;
    const float* xp0 = x + (size_t)node0 * DD;
    const float* xp1 = x + (size_t)node1 * DD;
    #pragma unroll
    for (int ct = 0; ct < 16; ct++) {
        int colb = ct * 8 + q * 2;
        float bb0 = sBias[colb], bb1 = sBias[colb + 1];
        float v0 = (c[ct][0] + bb0) * rsi0;
        float v1 = (c[ct][1] + bb1) * rsi0;
        float v2 = (c[ct][2] + bb0) * rsi1;
        float v3 = (c[ct][3] + bb1) * rsi1;
        float xa0 = (r0 < m) ? xp0[colb]     : 0.f;
        float xa1 = (r0 < m) ? xp0[colb + 1] : 0.f;
        float xb0 = (r1 < m) ? xp1[colb]     : 0.f;
        float xb1 = (r1 < m) ? xp1[colb + 1] : 0.f;
        dot0 += v0 * xa0 + v1 * xa1;
        nr0  += v0 * v0 + v1 * v1;
        nx0  += xa0 * xa0 + xa1 * xa1;
        dot1 += v2 * xb0 + v3 * xb1;
        nr1  += v2 * v2 + v3 * v3;
        nx1  += xb0 * xb0 + xb1 * xb1;
    }
    #pragma unroll
    for (int o = 1; o <= 2; o <<= 1) {
        dot0 += __shfl_xor_sync(0xffffffffu, dot0, o);
        nr0  += __shfl_xor_sync(0xffffffffu, nr0,  o);
        nx0  += __shfl_xor_sync(0xffffffffu, nx0,  o);
        dot1 += __shfl_xor_sync(0xffffffffu, dot1, o);
        nr1  += __shfl_xor_sync(0xffffffffu, nr1,  o);
        nx1  += __shfl_xor_sync(0xffffffffu, nx1,  o);
    }
    float term = 0.f;
    if (q == 0) {
        if (r0 < m) {
            float cc = dot0 / (fmaxf(sqrtf(nr0), 1e-12f) * fmaxf(sqrtf(nx0), 1e-12f));
            float t = 1.f - cc;
            term += t * t;
        }
        if (r1 < m) {
            float cc = dot1 / (fmaxf(sqrtf(nr1), 1e-12f) * fmaxf(sqrtf(nx1), 1e-12f));
            float t = 1.f - cc;
            term += t * t;
        }
    }
    #pragma unroll
    for (int o = 4; o <= 16; o <<= 1) term += __shfl_xor_sync(0xffffffffu, term, o);
    if (lane == 0) sWsum[warp] = term;
    __syncthreads();
    if (tid == 0) {
        float s = 0.f;
        #pragma unroll
        for (int i = 0; i < 8; i++) s += sWsum[i];
        atomicAdd(out, s / (float)m);
    }
}

// ---------------- launch ----------------
extern "C" void kernel_launch(void* const* d_in, const int* in_sizes, int n_in,
                              void* d_out, int out_size) {
    const float* x     = (const float*)d_in[0];
    const float* token = (const float*)d_in[1];
    const float* W1    = (const float*)d_in[2];
    const float* b1    = (const float*)d_in[3];
    const float* g1    = (const float*)d_in[4];
    const float* be1   = (const float*)d_in[5];
    const float* a1    = (const float*)d_in[6];
    const float* W2    = (const float*)d_in[7];
    const float* b2    = (const float*)d_in[8];
    const float* g2    = (const float*)d_in[9];
    const float* be2   = (const float*)d_in[10];
    const float* a2    = (const float*)d_in[11];
    const float* We2d  = (const float*)d_in[12];
    const float* Wd    = (const float*)d_in[13];
    const float* bd    = (const float*)d_in[14];
    const int*   src   = (const int*)d_in[15];
    const int*   dst   = (const int*)d_in[16];
    const int*   mask  = (const int*)d_in[17];

    const int n = in_sizes[0] / DD;
    const int E = in_sizes[15];
    const int M = in_sizes[17];
    const int NM = n - M;               // non-masked node count (mask indices are unique)
    float* out = (float*)d_out;

    float *tokA, *rs_out, *rs_in;
    __half *S, *agg16;
    int *deg_out, *deg_in, *maskflag, *rowptr, *eslot, *csrc, *bsum, *nonmask, *nmcount;
    cudaGetSymbolAddress((void**)&S,     g_S);
    cudaGetSymbolAddress((void**)&agg16, g_agg16);
    cudaGetSymbolAddress((void**)&tokA,  g_token);
    cudaGetSymbolAddress((void**)&deg_out, g_deg_out);
    cudaGetSymbolAddress((void**)&deg_in,  g_deg_in);
    cudaGetSymbolAddress((void**)&rs_out, g_rs_out);
    cudaGetSymbolAddress((void**)&rs_in,  g_rs_in);
    cudaGetSymbolAddress((void**)&maskflag, g_maskflag);
    cudaGetSymbolAddress((void**)&rowptr, g_rowptr);
    cudaGetSymbolAddress((void**)&eslot,  g_eslot);
    cudaGetSymbolAddress((void**)&csrc,   g_csrc);
    cudaGetSymbolAddress((void**)&bsum,   g_bsum);
    cudaGetSymbolAddress((void**)&nonmask, g_nonmask);
    cudaGetSymbolAddress((void**)&nmcount, g_nmcount);

    const size_t smem = (size_t)(2 * 128 * SROW) * sizeof(__half) + 3 * 128 * sizeof(float);
    cudaFuncSetAttribute(k_gemm1, cudaFuncAttributeMaxDynamicSharedMemorySize, (int)smem);
    cudaFuncSetAttribute(k_gemm_fused, cudaFuncAttributeMaxDynamicSharedMemorySize, (int)smem);
    cudaFuncSetAttribute(k_gemm_loss, cudaFuncAttributeMaxDynamicSharedMemorySize, (int)smem);

    const int T = 256;
    const int gE  = (E + T - 1) / T;
    const int gW  = ((n * 32) + T - 1) / T;
    const int gWM = ((M * 32) + T - 1) / T;
    const int gWN = ((NM * 32) + T - 1) / T;
    const int gG  = (n + 127) / 128;
    const int gGN = (NM + 127) / 128;
    const int gGM = (M + 127) / 128;
    const int nb  = (n + 1 + 1023) / 1024;

    // CSR build (deg arrays arrive zeroed: zero-init on first call, tail-zeroed per replay)
    k_deg  <<<gE, T>>>(src, dst, deg_out, deg_in, eslot, E);
    k_scan1<<<nb, 1024>>>(deg_in, deg_out, rowptr, bsum, mask, maskflag, M,
                          rs_out, rs_in, token, tokA, out, n);
    k_scan3<<<nb, 1024>>>(rowptr, bsum, maskflag, nonmask, nmcount, n);
    k_fill <<<gE, T>>>(src, dst, rowptr, eslot, csrc, E);

    // conv1 (all nodes)
    k_prep1<<<gW, T>>>(x, tokA, maskflag, rs_out, S, n);
    k_agg  <<<gW, T>>>(S, rowptr, csrc, agg16, n);
    k_gemm1<<<gG, 256, smem>>>(agg16, S, W1, b1, rs_in, rs_out, g1, be1, a1, n);

    // conv2 + enc->dec (compacted over non-masked nodes)
    k_agg_idx<<<gWN, T>>>(S, rowptr, csrc, maskflag, nonmask, agg16, NM, 0);
    k_gemm_fused<<<gGN, 256, smem>>>(agg16, S, W2, b2, We2d, rs_in, rs_out, g2, be2, a2, nonmask, NM);

    // decoder conv + loss (compacted over masked nodes, skip masked src) + tail cleanup
    k_agg_idx<<<gWM, T>>>(S, rowptr, csrc, maskflag, mask, agg16, M, 1);
    k_gemm_loss<<<gGM, 256, smem>>>(agg16, x, mask, Wd, bd, rs_in, M, out,
                                    deg_out, deg_in, maskflag, nmcount, n);
}

// round 15
// speedup vs baseline: 1.5061x; 1.0116x over previous
#include <cuda_runtime.h>
#include <cuda_fp16.h>
#include <cstdint>
#include <stdint.h>
#include <math.h>

#define DD 128
#define NMAX 50000
#define EMAX 800000
#define SROW 136            // smem row stride in halfs (272B, 16B-multiple)

// ---------------- scratch (static device globals; zero-initialized at load,
// re-zeroed by the tail of every launch for the next replay) ----------------
__device__ __align__(16) __half g_S[(size_t)NMAX * DD];       // rs_out-scaled gather rows
__device__ __align__(16) __half g_agg16[(size_t)NMAX * DD];   // aggregation output (fp16)
__device__ __align__(16) float  g_token[DD];
__device__ int   g_deg_out[NMAX];     // must be 0 at launch start
__device__ int   g_deg_in[NMAX];      // must be 0 at launch start
__device__ float g_rs_out[NMAX];
__device__ float g_rs_in[NMAX];
__device__ int   g_maskflag[NMAX];    // must be 0 at launch start
__device__ int   g_rowptr[NMAX + 1];
__device__ int   g_bsum[128];
__device__ int   g_nonmask[NMAX];
__device__ int   g_nmcount;           // must be 0 at launch start
__device__ int   g_eslot[EMAX];
__device__ int   g_csrc[EMAX];

// ---------------- k_deg: degree count; atomic return value = CSR fill slot ----------------
__global__ void k_deg(const int* __restrict__ src, const int* __restrict__ dst,
                      int* __restrict__ dout, int* __restrict__ din,
                      int* __restrict__ eslot, int e) {
    int i = blockIdx.x * blockDim.x + threadIdx.x;
    if (i < e) {
        atomicAdd(&dout[src[i]], 1);
        eslot[i] = atomicAdd(&din[dst[i]], 1);
    }
}

// ---------------- k_scan1: per-tile exclusive scan + rsqrt + mask mark + token + out ----
__global__ void __launch_bounds__(1024)
k_scan1(const int* __restrict__ din, const int* __restrict__ dout,
        int* __restrict__ rowptr, int* __restrict__ bsum,
        const int* __restrict__ mask_nodes, int* __restrict__ maskflag, int m,
        float* __restrict__ ro, float* __restrict__ ri,
        const float* __restrict__ token, float* __restrict__ tok,
        float* __restrict__ out, int n) {
    __shared__ int warpsum[32];
    int t = threadIdx.x;
    int gi = blockIdx.x * 1024 + t;
    int lane = t & 31, wid = t >> 5;

    int v = (gi < n) ? din[gi] : 0;

    if (gi < n) {
        ro[gi] = rsqrtf(fmaxf((float)dout[gi], 1.f));
        ri[gi] = rsqrtf(fmaxf((float)v, 1.f));
    }
    if (gi < m) maskflag[mask_nodes[gi]] = 1;
    if (gi < DD) tok[gi] = token[gi];
    if (gi == 0) out[0] = 0.f;

    int inc = v;
    #pragma unroll
    for (int o = 1; o < 32; o <<= 1) {
        int u = __shfl_up_sync(0xffffffffu, inc, o);
        if (lane >= o) inc += u;
    }
    if (lane == 31) warpsum[wid] = inc;
    __syncthreads();
    if (wid == 0) {
        int w = warpsum[lane];
        #pragma unroll
        for (int o = 1; o < 32; o <<= 1) {
            int u = __shfl_up_sync(0xffffffffu, w, o);
            if (lane >= o) w += u;
        }
        warpsum[lane] = w;
    }
    __syncthreads();
    int woff = (wid > 0) ? warpsum[wid - 1] : 0;
    if (gi <= n) rowptr[gi] = woff + inc - v;
    if (t == 1023) bsum[blockIdx.x] = warpsum[31];
}

// ---------------- k_scan3: add block offsets + build nonmask list ----------------
__global__ void __launch_bounds__(1024)
k_scan3(int* __restrict__ rowptr, const int* __restrict__ bsum,
        const int* __restrict__ maskflag, int* __restrict__ nonmask,
        int* __restrict__ nmcount, int n) {
    __shared__ int soff;
    int t = threadIdx.x;
    if (t < 32) {
        int ssum = 0;
        for (int i = t; i < blockIdx.x; i += 32) ssum += bsum[i];
        #pragma unroll
        for (int o = 16; o; o >>= 1) ssum += __shfl_xor_sync(0xffffffffu, ssum, o);
        if (t == 0) soff = ssum;
    }
    __syncthreads();
    int gi = blockIdx.x * 1024 + t;
    if (gi <= n) rowptr[gi] += soff;
    if (gi < n && !maskflag[gi]) {
        int p = atomicAdd(nmcount, 1);
        nonmask[p] = gi;
    }
}

// ---------------- fused CSR fill (atomic-free) + conv1 prep ----------------
// thread i < E: csrc[rowptr[dst]+eslot] = src (scattered stores)
// warp w < n: S[w] = (mask? token : x[w]) * rs_out[w] as fp16 (streaming)
__global__ void __launch_bounds__(256)
k_fill_prep(const int* __restrict__ src, const int* __restrict__ dst,
            const int* __restrict__ rowptr, const int* __restrict__ eslot,
            int* __restrict__ csrc, int e,
            const float* __restrict__ x, const float* __restrict__ token,
            const int* __restrict__ maskflag, const float* __restrict__ rs_out,
            __half* __restrict__ S, int n) {
    int i = blockIdx.x * blockDim.x + threadIdx.x;
    if (i < e) {
        int d = dst[i];
        csrc[rowptr[d] + eslot[i]] = src[i];
    }
    int w = i >> 5;
    int lane = i & 31;
    if (w < n) {
        float r = rs_out[w];
        const float* srcp = maskflag[w] ? (token + lane * 4) : (x + (size_t)w * DD + lane * 4);
        __half2 p0 = __floats2half2_rn(srcp[0] * r, srcp[1] * r);
        __half2 p1 = __floats2half2_rn(srcp[2] * r, srcp[3] * r);
        uint2 u;
        *(__half2*)&u.x = p0;
        *(__half2*)&u.y = p1;
        ((uint2*)S)[(size_t)w * 32 + lane] = u;
    }
}

// ---------------- CSR aggregation over all nodes (4-edge unrolled for MLP) ----------------
__global__ void __launch_bounds__(256)
k_agg(const __half* __restrict__ S,
      const int* __restrict__ rowptr, const int* __restrict__ csrc,
      __half* __restrict__ agg, int n) {
    int w = (blockIdx.x * blockDim.x + threadIdx.x) >> 5;
    int lane = threadIdx.x & 31;
    if (w >= n) return;
    int beg = rowptr[w];
    int end = rowptr[w + 1];
    float4 acc = make_float4(0.f, 0.f, 0.f, 0.f);
    int e = beg;
    for (; e + 3 < end; e += 4) {
        int s0 = csrc[e], s1 = csrc[e + 1], s2 = csrc[e + 2], s3 = csrc[e + 3];
        uint2 u0 = ((const uint2*)S)[(size_t)s0 * 32 + lane];
        uint2 u1 = ((const uint2*)S)[(size_t)s1 * 32 + lane];
        uint2 u2 = ((const uint2*)S)[(size_t)s2 * 32 + lane];
        uint2 u3 = ((const uint2*)S)[(size_t)s3 * 32 + lane];
        float2 a0 = __half22float2(*(__half2*)&u0.x), b0 = __half22float2(*(__half2*)&u0.y);
        float2 a1 = __half22float2(*(__half2*)&u1.x), b1 = __half22float2(*(__half2*)&u1.y);
        float2 a2 = __half22float2(*(__half2*)&u2.x), b2 = __half22float2(*(__half2*)&u2.y);
        float2 a3 = __half22float2(*(__half2*)&u3.x), b3 = __half22float2(*(__half2*)&u3.y);
        acc.x += (a0.x + a1.x) + (a2.x + a3.x);
        acc.y += (a0.y + a1.y) + (a2.y + a3.y);
        acc.z += (b0.x + b1.x) + (b2.x + b3.x);
        acc.w += (b0.y + b1.y) + (b2.y + b3.y);
    }
    for (; e < end; e++) {
        int s = csrc[e];
        uint2 u = ((const uint2*)S)[(size_t)s * 32 + lane];
        float2 f0 = __half22float2(*(__half2*)&u.x);
        float2 f1 = __half22float2(*(__half2*)&u.y);
        acc.x += f0.x; acc.y += f0.y; acc.z += f1.x; acc.w += f1.y;
    }
    uint2 o;
    *(__half2*)&o.x = __floats2half2_rn(acc.x, acc.y);
    *(__half2*)&o.y = __floats2half2_rn(acc.z, acc.w);
    ((uint2*)agg)[(size_t)w * 32 + lane] = o;
}

// ---------------- indexed CSR aggregation (compacted over idxlist) ----------------
// skip_masked=0: 4-edge unrolled path; skip_masked=1 (decoder): simple loop with flag skip.
__global__ void __launch_bounds__(256)
k_agg_idx(const __half* __restrict__ S,
          const int* __restrict__ rowptr, const int* __restrict__ csrc,
          const int* __restrict__ maskflag, const int* __restrict__ idxlist,
          __half* __restrict__ agg, int cnt, int skip_masked) {
    int j = (blockIdx.x * blockDim.x + threadIdx.x) >> 5;
    int lane = threadIdx.x & 31;
    if (j >= cnt) return;
    int node = idxlist[j];
    int beg = rowptr[node];
    int end = rowptr[node + 1];
    float4 acc = make_float4(0.f, 0.f, 0.f, 0.f);
    if (!skip_masked) {
        int e = beg;
        for (; e + 3 < end; e += 4) {
            int s0 = csrc[e], s1 = csrc[e + 1], s2 = csrc[e + 2], s3 = csrc[e + 3];
            uint2 u0 = ((const uint2*)S)[(size_t)s0 * 32 + lane];
            uint2 u1 = ((const uint2*)S)[(size_t)s1 * 32 + lane];
            uint2 u2 = ((const uint2*)S)[(size_t)s2 * 32 + lane];
            uint2 u3 = ((const uint2*)S)[(size_t)s3 * 32 + lane];
            float2 a0 = __half22float2(*(__half2*)&u0.x), b0 = __half22float2(*(__half2*)&u0.y);
            float2 a1 = __half22float2(*(__half2*)&u1.x), b1 = __half22float2(*(__half2*)&u1.y);
            float2 a2 = __half22float2(*(__half2*)&u2.x), b2 = __half22float2(*(__half2*)&u2.y);
            float2 a3 = __half22float2(*(__half2*)&u3.x), b3 = __half22float2(*(__half2*)&u3.y);
            acc.x += (a0.x + a1.x) + (a2.x + a3.x);
            acc.y += (a0.y + a1.y) + (a2.y + a3.y);
            acc.z += (b0.x + b1.x) + (b2.x + b3.x);
            acc.w += (b0.y + b1.y) + (b2.y + b3.y);
        }
        for (; e < end; e++) {
            int s = csrc[e];
            uint2 u = ((const uint2*)S)[(size_t)s * 32 + lane];
            float2 f0 = __half22float2(*(__half2*)&u.x);
            float2 f1 = __half22float2(*(__half2*)&u.y);
            acc.x += f0.x; acc.y += f0.y; acc.z += f1.x; acc.w += f1.y;
        }
    } else {
        for (int e = beg; e < end; e++) {
            int s = csrc[e];
            if (maskflag[s]) continue;
            uint2 u = ((const uint2*)S)[(size_t)s * 32 + lane];
            float2 f0 = __half22float2(*(__half2*)&u.x);
            float2 f1 = __half22float2(*(__half2*)&u.y);
            acc.x += f0.x; acc.y += f0.y; acc.z += f1.x; acc.w += f1.y;
        }
    }
    uint2 o;
    *(__half2*)&o.x = __floats2half2_rn(acc.x, acc.y);
    *(__half2*)&o.y = __floats2half2_rn(acc.z, acc.w);
    ((uint2*)agg)[(size_t)j * 32 + lane] = o;
}

// ---------------- mma helper macros ----------------
#define MMA_LOOP(cacc, aBase, sWu, bRow, bKoff)                                              \
    _Pragma("unroll")                                                                         \
    for (int kb = 0; kb < 8; kb++) {                                                          \
        uint32_t a0, a1, a2, a3;                                                              \
        asm volatile("ldmatrix.sync.aligned.m8n8.x4.shared.b16 {%0,%1,%2,%3}, [%4];"         \
                     : "=r"(a0), "=r"(a1), "=r"(a2), "=r"(a3)                                 \
                     : "r"((aBase) + kb * 32));                                               \
        _Pragma("unroll")                                                                     \
        for (int ng = 0; ng < 8; ng++) {                                                      \
            uint32_t b0, b1, b2, b3;                                                          \
            uint32_t baddr = (sWu) + (uint32_t)((ng * 16 + (bRow)) * (SROW * 2) + kb * 32 + (bKoff)); \
            asm volatile("ldmatrix.sync.aligned.m8n8.x4.shared.b16 {%0,%1,%2,%3}, [%4];"     \
                         : "=r"(b0), "=r"(b1), "=r"(b2), "=r"(b3)                             \
                         : "r"(baddr));                                                       \
            int t0 = ng * 2, t1 = ng * 2 + 1;                                                 \
            asm volatile("mma.sync.aligned.m16n8k16.row.col.f32.f16.f16.f32 "                \
                         "{%0,%1,%2,%3}, {%4,%5,%6,%7}, {%8,%9}, {%0,%1,%2,%3};"             \
                         : "+f"(cacc[t0][0]), "+f"(cacc[t0][1]), "+f"(cacc[t0][2]), "+f"(cacc[t0][3]) \
                         : "r"(a0), "r"(a1), "r"(a2), "r"(a3), "r"(b0), "r"(b1));             \
            asm volatile("mma.sync.aligned.m16n8k16.row.col.f32.f16.f16.f32 "                \
                         "{%0,%1,%2,%3}, {%4,%5,%6,%7}, {%8,%9}, {%0,%1,%2,%3};"             \
                         : "+f"(cacc[t1][0]), "+f"(cacc[t1][1]), "+f"(cacc[t1][2]), "+f"(cacc[t1][3]) \
                         : "r"(a0), "r"(a1), "r"(a2), "r"(a3), "r"(b2), "r"(b3));             \
        }                                                                                     \
    }

#define STAGE_W(Wp, sW)                                                                       \
    _Pragma("unroll")                                                                         \
    for (int it = 0; it < 32; it++) {                                                         \
        int idx = it * 256 + threadIdx.x;                                                     \
        int base2 = idx * 2;                                                                  \
        int cc = base2 >> 7, kk = base2 & 127;                                                \
        float w0 = (Wp)[base2], w1 = (Wp)[base2 + 1];                                         \
        *(__half2*)&(sW)[cc * SROW + kk] = __floats2half2_rn(w0, w1);                         \
    }

#define STAGE_A(inp, sA, nrows)                                                               \
    _Pragma("unroll")                                                                         \
    for (int it = 0; it < 8; it++) {                                                          \
        int idx = it * 256 + threadIdx.x;                                                     \
        int r = idx >> 4, c8 = idx & 15;                                                      \
        uint4 v = make_uint4(0u, 0u, 0u, 0u);                                                 \
        int gr = row0 + r;                                                                    \
        if (gr < (nrows)) v = ((const uint4*)(inp))[(size_t)gr * 16 + c8];                    \
        *(uint4*)&(sA)[r * SROW + c8 * 8] = v;                                                \
    }

// ---------------- conv1 GEMM: (acc+b)*rs_in -> LN -> PReLU -> fp16 *rs_out -> S ----------
__global__ void __launch_bounds__(256, 2)
k_gemm1(const __half* __restrict__ in, __half* __restrict__ outh,
        const float* __restrict__ W, const float* __restrict__ bias,
        const float* __restrict__ rs_in, const float* __restrict__ rs_out,
        const float* __restrict__ gamma, const float* __restrict__ beta,
        const float* __restrict__ alpha, int n) {
    extern __shared__ char smraw[];
    __half* sA = (__half*)smraw;
    __half* sW = sA + 128 * SROW;
    float* sBias  = (float*)(sW + 128 * SROW);
    float* sGamma = sBias + 128;
    float* sBeta  = sGamma + 128;

    const int tid  = threadIdx.x;
    const int row0 = blockIdx.x * 128;

    STAGE_A(in, sA, n);
    STAGE_W(W, sW);
    if (tid < 128) { sBias[tid] = bias[tid]; sGamma[tid] = gamma[tid]; sBeta[tid] = beta[tid]; }
    __syncthreads();

    const int warp = tid >> 5;
    const int lane = tid & 31;
    float c[16][4];
    #pragma unroll
    for (int i = 0; i < 16; i++) { c[i][0]=0.f; c[i][1]=0.f; c[i][2]=0.f; c[i][3]=0.f; }

    uint32_t sAu = (uint32_t)__cvta_generic_to_shared(sA);
    uint32_t sWu = (uint32_t)__cvta_generic_to_shared(sW);
    uint32_t aBase = sAu + (uint32_t)((warp * 16 + (lane & 15)) * (SROW * 2) + (lane >> 4) * 16);
    uint32_t bRow  = (uint32_t)((lane >> 4) * 8 + (lane & 7));
    uint32_t bKoff = (uint32_t)(((lane >> 3) & 1) * 16);

    MMA_LOOP(c, aBase, sWu, bRow, bKoff);

    int r0 = row0 + warp * 16 + (lane >> 2);
    int r1 = r0 + 8;
    int q  = lane & 3;

    float rsi0 = (r0 < n) ? rs_in[r0] : 1.f;
    float rsi1 = (r1 < n) ? rs_in[r1] : 1.f;
    float s0 = 0.f, ss0 = 0.f, s1 = 0.f, ss1 = 0.f;
    #pragma unroll
    for (int ct = 0; ct < 16; ct++) {
        int colb = ct * 8 + q * 2;
        float bb0 = sBias[colb], bb1 = sBias[colb + 1];
        c[ct][0] = (c[ct][0] + bb0) * rsi0;
        c[ct][1] = (c[ct][1] + bb1) * rsi0;
        c[ct][2] = (c[ct][2] + bb0) * rsi1;
        c[ct][3] = (c[ct][3] + bb1) * rsi1;
        s0  += c[ct][0] + c[ct][1];
        ss0 += c[ct][0] * c[ct][0] + c[ct][1] * c[ct][1];
        s1  += c[ct][2] + c[ct][3];
        ss1 += c[ct][2] * c[ct][2] + c[ct][3] * c[ct][3];
    }
    #pragma unroll
    for (int o = 1; o <= 2; o <<= 1) {
        s0  += __shfl_xor_sync(0xffffffffu, s0,  o);
        ss0 += __shfl_xor_sync(0xffffffffu, ss0, o);
        s1  += __shfl_xor_sync(0xffffffffu, s1,  o);
        ss1 += __shfl_xor_sync(0xffffffffu, ss1, o);
    }
    float mu0 = s0 * (1.f / 128.f);
    float mu1 = s1 * (1.f / 128.f);
    float inv0 = rsqrtf(ss0 * (1.f / 128.f) - mu0 * mu0 + 1e-5f);
    float inv1 = rsqrtf(ss1 * (1.f / 128.f) - mu1 * mu1 + 1e-5f);
    float aP = alpha[0];
    float rso0 = (r0 < n) ? rs_out[r0] : 1.f;
    float rso1 = (r1 < n) ? rs_out[r1] : 1.f;
    #pragma unroll
    for (int ct = 0; ct < 16; ct++) {
        int colb = ct * 8 + q * 2;
        float g0 = sGamma[colb], g1 = sGamma[colb + 1];
        float e0 = sBeta[colb],  e1 = sBeta[colb + 1];
        float y0 = (c[ct][0] - mu0) * inv0 * g0 + e0; y0 = (y0 >= 0.f) ? y0 : aP * y0;
        float y1 = (c[ct][1] - mu0) * inv0 * g1 + e1; y1 = (y1 >= 0.f) ? y1 : aP * y1;
        float y2 = (c[ct][2] - mu1) * inv1 * g0 + e0; y2 = (y2 >= 0.f) ? y2 : aP * y2;
        float y3 = (c[ct][3] - mu1) * inv1 * g1 + e1; y3 = (y3 >= 0.f) ? y3 : aP * y3;
        int ci = ct * 4 + q;
        if (r0 < n) ((__half2*)outh)[(size_t)r0 * 64 + ci] = __floats2half2_rn(y0 * rso0, y1 * rso0);
        if (r1 < n) ((__half2*)outh)[(size_t)r1 * 64 + ci] = __floats2half2_rn(y2 * rso1, y3 * rso1);
    }
}

// ---------------- fused conv2-GEMM (LN+PReLU) + enc->dec-GEMM (*rs_out), compacted ----------
__global__ void __launch_bounds__(256, 2)
k_gemm_fused(const __half* __restrict__ in, __half* __restrict__ outS,
             const float* __restrict__ W2, const float* __restrict__ bias2,
             const float* __restrict__ We2d,
             const float* __restrict__ rs_in, const float* __restrict__ rs_out,
             const float* __restrict__ gamma, const float* __restrict__ beta,
             const float* __restrict__ alpha,
             const int* __restrict__ nonmask, int nm) {
    extern __shared__ char smraw[];
    __half* sA = (__half*)smraw;
    __half* sW = sA + 128 * SROW;
    float* sBias  = (float*)(sW + 128 * SROW);
    float* sGamma = sBias + 128;
    float* sBeta  = sGamma + 128;

    const int tid  = threadIdx.x;
    const int row0 = blockIdx.x * 128;

    STAGE_A(in, sA, nm);
    STAGE_W(W2, sW);
    if (tid < 128) { sBias[tid] = bias2[tid]; sGamma[tid] = gamma[tid]; sBeta[tid] = beta[tid]; }
    __syncthreads();

    const int warp = tid >> 5;
    const int lane = tid & 31;
    float c[16][4];
    #pragma unroll
    for (int i = 0; i < 16; i++) { c[i][0]=0.f; c[i][1]=0.f; c[i][2]=0.f; c[i][3]=0.f; }

    uint32_t sAu = (uint32_t)__cvta_generic_to_shared(sA);
    uint32_t sWu = (uint32_t)__cvta_generic_to_shared(sW);
    uint32_t aBase = sAu + (uint32_t)((warp * 16 + (lane & 15)) * (SROW * 2) + (lane >> 4) * 16);
    uint32_t bRow  = (uint32_t)((lane >> 4) * 8 + (lane & 7));
    uint32_t bKoff = (uint32_t)(((lane >> 3) & 1) * 16);

    MMA_LOOP(c, aBase, sWu, bRow, bKoff);

    int lr0 = warp * 16 + (lane >> 2);
    int lr1 = lr0 + 8;
    int r0 = row0 + lr0;
    int r1 = row0 + lr1;
    int q  = lane & 3;

    int node0 = (r0 < nm) ? nonmask[r0] : 0;
    int node1 = (r1 < nm) ? nonmask[r1] : 0;
    float rsi0 = (r0 < nm) ? rs_in[node0] : 1.f;
    float rsi1 = (r1 < nm) ? rs_in[node1] : 1.f;
    float s0 = 0.f, ss0 = 0.f, s1 = 0.f, ss1 = 0.f;
    #pragma unroll
    for (int ct = 0; ct < 16; ct++) {
        int colb = ct * 8 + q * 2;
        float bb0 = sBias[colb], bb1 = sBias[colb + 1];
        c[ct][0] = (c[ct][0] + bb0) * rsi0;
        c[ct][1] = (c[ct][1] + bb1) * rsi0;
        c[ct][2] = (c[ct][2] + bb0) * rsi1;
        c[ct][3] = (c[ct][3] + bb1) * rsi1;
        s0  += c[ct][0] + c[ct][1];
        ss0 += c[ct][0] * c[ct][0] + c[ct][1] * c[ct][1];
        s1  += c[ct][2] + c[ct][3];
        ss1 += c[ct][2] * c[ct][2] + c[ct][3] * c[ct][3];
    }
    #pragma unroll
    for (int o = 1; o <= 2; o <<= 1) {
        s0  += __shfl_xor_sync(0xffffffffu, s0,  o);
        ss0 += __shfl_xor_sync(0xffffffffu, ss0, o);
        s1  += __shfl_xor_sync(0xffffffffu, s1,  o);
        ss1 += __shfl_xor_sync(0xffffffffu, ss1, o);
    }
    float mu0 = s0 * (1.f / 128.f);
    float mu1 = s1 * (1.f / 128.f);
    float inv0 = rsqrtf(ss0 * (1.f / 128.f) - mu0 * mu0 + 1e-5f);
    float inv1 = rsqrtf(ss1 * (1.f / 128.f) - mu1 * mu1 + 1e-5f);
    float aP = alpha[0];
    #pragma unroll
    for (int ct = 0; ct < 16; ct++) {
        int colb = ct * 8 + q * 2;
        float g0 = sGamma[colb], g1 = sGamma[colb + 1];
        float e0 = sBeta[colb],  e1 = sBeta[colb + 1];
        float y0 = (c[ct][0] - mu0) * inv0 * g0 + e0; y0 = (y0 >= 0.f) ? y0 : aP * y0;
        float y1 = (c[ct][1] - mu0) * inv0 * g1 + e1; y1 = (y1 >= 0.f) ? y1 : aP * y1;
        float y2 = (c[ct][2] - mu1) * inv1 * g0 + e0; y2 = (y2 >= 0.f) ? y2 : aP * y2;
        float y3 = (c[ct][3] - mu1) * inv1 * g1 + e1; y3 = (y3 >= 0.f) ? y3 : aP * y3;
        *(__half2*)&sA[lr0 * SROW + colb] = __floats2half2_rn(y0, y1);
        *(__half2*)&sA[lr1 * SROW + colb] = __floats2half2_rn(y2, y3);
    }

    __syncthreads();
    STAGE_W(We2d, sW);
    __syncthreads();

    #pragma unroll
    for (int i = 0; i < 16; i++) { c[i][0]=0.f; c[i][1]=0.f; c[i][2]=0.f; c[i][3]=0.f; }
    MMA_LOOP(c, aBase, sWu, bRow, bKoff);

    float rso0 = (r0 < nm) ? rs_out[node0] : 0.f;
    float rso1 = (r1 < nm) ? rs_out[node1] : 0.f;
    #pragma unroll
    for (int ct = 0; ct < 16; ct++) {
        int ci = ct * 4 + q;
        if (r0 < nm) ((__half2*)outS)[(size_t)node0 * 64 + ci] = __floats2half2_rn(c[ct][0] * rso0, c[ct][1] * rso0);
        if (r1 < nm) ((__half2*)outS)[(size_t)node1 * 64 + ci] = __floats2half2_rn(c[ct][2] * rso1, c[ct][3] * rso1);
    }
}

// ---------------- decoder GEMM + fused SCE loss + tail cleanup for next replay ----------
__global__ void __launch_bounds__(256, 2)
k_gemm_loss(const __half* __restrict__ in, const float* __restrict__ x,
            const int* __restrict__ mask_nodes,
            const float* __restrict__ W, const float* __restrict__ bias,
            const float* __restrict__ rs_in,
            int m, float* __restrict__ out,
            int* __restrict__ deg_out, int* __restrict__ deg_in,
            int* __restrict__ maskflag, int* __restrict__ nmcount, int n) {
    extern __shared__ char smraw[];
    __half* sA = (__half*)smraw;
    __half* sW = sA + 128 * SROW;
    float* sBias = (float*)(sW + 128 * SROW);
    float* sWsum = sBias + 128;     // [8] warp partial sums

    const int tid  = threadIdx.x;
    const int row0 = blockIdx.x * 128;

    // tail cleanup: restore zero-state invariants for the next graph replay
    for (int i = blockIdx.x * blockDim.x + tid; i < n; i += gridDim.x * blockDim.x) {
        deg_out[i] = 0; deg_in[i] = 0; maskflag[i] = 0;
    }
    if (blockIdx.x == 0 && tid == 0) *nmcount = 0;

    STAGE_A(in, sA, m);
    STAGE_W(W, sW);
    if (tid < 128) sBias[tid] = bias[tid];
    __syncthreads();

    const int warp = tid >> 5;
    const int lane = tid & 31;
    float c[16][4];
    #pragma unroll
    for (int i = 0; i < 16; i++) { c[i][0]=0.f; c[i][1]=0.f; c[i][2]=0.f; c[i][3]=0.f; }

    uint32_t sAu = (uint32_t)__cvta_generic_to_shared(sA);
    uint32_t sWu = (uint32_t)__cvta_generic_to_shared(sW);
    uint32_t aBase = sAu + (uint32_t)((warp * 16 + (lane & 15)) * (SROW * 2) + (lane >> 4) * 16);
    uint32_t bRow  = (uint32_t)((lane >> 4) * 8 + (lane & 7));
    uint32_t bKoff = (uint32_t)(((lane >> 3) & 1) * 16);

    MMA_LOOP(c, aBase, sWu, bRow, bKoff);

    int r0 = row0 + warp * 16 + (lane >> 2);   // compacted row index
    int r1 = r0 + 8;
    int q  = lane & 3;

    int node0 = (r0 < m) ? mask_nodes[r0] : 0;
    int node1 = (r1 < m) ? mask_nodes[r1] : 0;
    float rsi0 = (r0 < m) ? rs_in[node0] : 0.f;
    float rsi1 = (r1 < m) ? rs_in[node1] : 0.f;

    float dot0 = 0.f, nr0 = 0.f, nx0 = 0.f;
    float dot1 = 0.f, nr1 = 0.f, nx1 = 0.f;
    const float* xp0 = x + (size_t)node0 * DD;
    const float* xp1 = x + (size_t)node1 * DD;
    #pragma unroll
    for (int ct = 0; ct < 16; ct++) {
        int colb = ct * 8 + q * 2;
        float bb0 = sBias[colb], bb1 = sBias[colb + 1];
        float v0 = (c[ct][0] + bb0) * rsi0;
        float v1 = (c[ct][1] + bb1) * rsi0;
        float v2 = (c[ct][2] + bb0) * rsi1;
        float v3 = (c[ct][3] + bb1) * rsi1;
        float xa0 = (r0 < m) ? xp0[colb]     : 0.f;
        float xa1 = (r0 < m) ? xp0[colb + 1] : 0.f;
        float xb0 = (r1 < m) ? xp1[colb]     : 0.f;
        float xb1 = (r1 < m) ? xp1[colb + 1] : 0.f;
        dot0 += v0 * xa0 + v1 * xa1;
        nr0  += v0 * v0 + v1 * v1;
        nx0  += xa0 * xa0 + xa1 * xa1;
        dot1 += v2 * xb0 + v3 * xb1;
        nr1  += v2 * v2 + v3 * v3;
        nx1  += xb0 * xb0 + xb1 * xb1;
    }
    #pragma unroll
    for (int o = 1; o <= 2; o <<= 1) {
        dot0 += __shfl_xor_sync(0xffffffffu, dot0, o);
        nr0  += __shfl_xor_sync(0xffffffffu, nr0,  o);
        nx0  += __shfl_xor_sync(0xffffffffu, nx0,  o);
        dot1 += __shfl_xor_sync(0xffffffffu, dot1, o);
        nr1  += __shfl_xor_sync(0xffffffffu, nr1,  o);
        nx1  += __shfl_xor_sync(0xffffffffu, nx1,  o);
    }
    float term = 0.f;
    if (q == 0) {
        if (r0 < m) {
            float cc = dot0 / (fmaxf(sqrtf(nr0), 1e-12f) * fmaxf(sqrtf(nx0), 1e-12f));
            float t = 1.f - cc;
            term += t * t;
        }
        if (r1 < m) {
            float cc = dot1 / (fmaxf(sqrtf(nr1), 1e-12f) * fmaxf(sqrtf(nx1), 1e-12f));
            float t = 1.f - cc;
            term += t * t;
        }
    }
    #pragma unroll
    for (int o = 4; o <= 16; o <<= 1) term += __shfl_xor_sync(0xffffffffu, term, o);
    if (lane == 0) sWsum[warp] = term;
    __syncthreads();
    if (tid == 0) {
        float s = 0.f;
        #pragma unroll
        for (int i = 0; i < 8; i++) s += sWsum[i];
        atomicAdd(out, s / (float)m);
    }
}

// ---------------- launch ----------------
extern "C" void kernel_launch(void* const* d_in, const int* in_sizes, int n_in,
                              void* d_out, int out_size) {
    const float* x     = (const float*)d_in[0];
    const float* token = (const float*)d_in[1];
    const float* W1    = (const float*)d_in[2];
    const float* b1    = (const float*)d_in[3];
    const float* g1    = (const float*)d_in[4];
    const float* be1   = (const float*)d_in[5];
    const float* a1    = (const float*)d_in[6];
    const float* W2    = (const float*)d_in[7];
    const float* b2    = (const float*)d_in[8];
    const float* g2    = (const float*)d_in[9];
    const float* be2   = (const float*)d_in[10];
    const float* a2    = (const float*)d_in[11];
    const float* We2d  = (const float*)d_in[12];
    const float* Wd    = (const float*)d_in[13];
    const float* bd    = (const float*)d_in[14];
    const int*   src   = (const int*)d_in[15];
    const int*   dst   = (const int*)d_in[16];
    const int*   mask  = (const int*)d_in[17];

    const int n = in_sizes[0] / DD;
    const int E = in_sizes[15];
    const int M = in_sizes[17];
    const int NM = n - M;               // non-masked node count (mask indices are unique)
    float* out = (float*)d_out;

    float *tokA, *rs_out, *rs_in;
    __half *S, *agg16;
    int *deg_out, *deg_in, *maskflag, *rowptr, *eslot, *csrc, *bsum, *nonmask, *nmcount;
    cudaGetSymbolAddress((void**)&S,     g_S);
    cudaGetSymbolAddress((void**)&agg16, g_agg16);
    cudaGetSymbolAddress((void**)&tokA,  g_token);
    cudaGetSymbolAddress((void**)&deg_out, g_deg_out);
    cudaGetSymbolAddress((void**)&deg_in,  g_deg_in);
    cudaGetSymbolAddress((void**)&rs_out, g_rs_out);
    cudaGetSymbolAddress((void**)&rs_in,  g_rs_in);
    cudaGetSymbolAddress((void**)&maskflag, g_maskflag);
    cudaGetSymbolAddress((void**)&rowptr, g_rowptr);
    cudaGetSymbolAddress((void**)&eslot,  g_eslot);
    cudaGetSymbolAddress((void**)&csrc,   g_csrc);
    cudaGetSymbolAddress((void**)&bsum,   g_bsum);
    cudaGetSymbolAddress((void**)&nonmask, g_nonmask);
    cudaGetSymbolAddress((void**)&nmcount, g_nmcount);

    const size_t smem = (size_t)(2 * 128 * SROW) * sizeof(__half) + 3 * 128 * sizeof(float);
    cudaFuncSetAttribute(k_gemm1, cudaFuncAttributeMaxDynamicSharedMemorySize, (int)smem);
    cudaFuncSetAttribute(k_gemm_fused, cudaFuncAttributeMaxDynamicSharedMemorySize, (int)smem);
    cudaFuncSetAttribute(k_gemm_loss, cudaFuncAttributeMaxDynamicSharedMemorySize, (int)smem);

    const int T = 256;
    const int gE  = (E + T - 1) / T;
    const int gW  = ((n * 32) + T - 1) / T;
    const int gWM = ((M * 32) + T - 1) / T;
    const int gWN = ((NM * 32) + T - 1) / T;
    const int gFP = (((n * 32 > E) ? n * 32 : E) + T - 1) / T;   // fill+prep merged grid
    const int gG  = (n + 127) / 128;
    const int gGN = (NM + 127) / 128;
    const int gGM = (M + 127) / 128;
    const int nb  = (n + 1 + 1023) / 1024;

    // CSR build + prep (deg arrays arrive zeroed: zero-init first call, tail-zeroed per replay)
    k_deg  <<<gE, T>>>(src, dst, deg_out, deg_in, eslot, E);
    k_scan1<<<nb, 1024>>>(deg_in, deg_out, rowptr, bsum, mask, maskflag, M,
                          rs_out, rs_in, token, tokA, out, n);
    k_scan3<<<nb, 1024>>>(rowptr, bsum, maskflag, nonmask, nmcount, n);
    k_fill_prep<<<gFP, T>>>(src, dst, rowptr, eslot, csrc, E,
                            x, tokA, maskflag, rs_out, S, n);

    // conv1 (all nodes)
    k_agg  <<<gW, T>>>(S, rowptr, csrc, agg16, n);
    k_gemm1<<<gG, 256, smem>>>(agg16, S, W1, b1, rs_in, rs_out, g1, be1, a1, n);

    // conv2 + enc->dec (compacted over non-masked nodes)
    k_agg_idx<<<gWN, T>>>(S, rowptr, csrc, maskflag, nonmask, agg16, NM, 0);
    k_gemm_fused<<<gGN, 256, smem>>>(agg16, S, W2, b2, We2d, rs_in, rs_out, g2, be2, a2, nonmask, NM);

    // decoder conv + loss (compacted over masked nodes, skip masked src) + tail cleanup
    k_agg_idx<<<gWM, T>>>(S, rowptr, csrc, maskflag, mask, agg16, M, 1);
    k_gemm_loss<<<gGM, 256, smem>>>(agg16, x, mask, Wd, bd, rs_in, M, out,
                                    deg_out, deg_in, maskflag, nmcount, n);
}